// round 1
// baseline (speedup 1.0000x reference)
#include <cuda_runtime.h>
#include <math.h>

#define N_IMG  128
#define N_REG  36
#define N_CAP  128
#define N_WORD 32
#define DIM    1024
#define LAMBDA 20.0f
#define EPSV   1e-8f
#define SLOPE  0.1f

#define M_TOT (N_IMG * N_REG)    // 4608
#define N_TOT (N_CAP * N_WORD)   // 4096

// scratch (no cudaMalloc allowed)
__device__ float d_S[(size_t)M_TOT * N_TOT];          // 75.5 MB, row-major [m][n]
__device__ float d_Gi[N_IMG * N_REG * N_REG];         // per-image Gram 36x36
__device__ float d_Gc[N_CAP * N_WORD * N_WORD];       // per-caption Gram 32x32

__device__ __forceinline__ float lrelu(float x) {
    return x > 0.f ? x : SLOPE * x;
}

// ---------------------------------------------------------------------------
// Stage 1: S = A @ B^T   (A: [4608,1024] images-flat, B: [4096,1024] captions-flat)
// classic 128x128x8 SGEMM, 256 threads, 8x8 per thread, output row-major to d_S
// ---------------------------------------------------------------------------
__global__ __launch_bounds__(256, 2)
void sgemm_kernel(const float* __restrict__ A, const float* __restrict__ B) {
    __shared__ float As[8][128];
    __shared__ float Bs[8][128];

    const int tid = threadIdx.x;
    const int mb = blockIdx.y * 128;
    const int nb = blockIdx.x * 128;

    const int loadRow = tid >> 1;           // 0..127
    const int loadK4  = (tid & 1) * 4;      // 0 or 4
    const float* Aptr = A + (size_t)(mb + loadRow) * DIM + loadK4;
    const float* Bptr = B + (size_t)(nb + loadRow) * DIM + loadK4;

    const int tx = tid & 15;                // n-dir
    const int ty = tid >> 4;                // m-dir
    const int tm0 = ty * 4;
    const int tn0 = tx * 4;

    float acc[8][8];
#pragma unroll
    for (int i = 0; i < 8; i++)
#pragma unroll
        for (int j = 0; j < 8; j++) acc[i][j] = 0.f;

    for (int k0 = 0; k0 < DIM; k0 += 8) {
        float4 av = *(const float4*)(Aptr + k0);
        float4 bv = *(const float4*)(Bptr + k0);
        __syncthreads();
        As[loadK4 + 0][loadRow] = av.x;
        As[loadK4 + 1][loadRow] = av.y;
        As[loadK4 + 2][loadRow] = av.z;
        As[loadK4 + 3][loadRow] = av.w;
        Bs[loadK4 + 0][loadRow] = bv.x;
        Bs[loadK4 + 1][loadRow] = bv.y;
        Bs[loadK4 + 2][loadRow] = bv.z;
        Bs[loadK4 + 3][loadRow] = bv.w;
        __syncthreads();
#pragma unroll
        for (int k = 0; k < 8; k++) {
            float a[8], b[8];
            *(float4*)(a)     = *(const float4*)&As[k][tm0];
            *(float4*)(a + 4) = *(const float4*)&As[k][tm0 + 64];
            *(float4*)(b)     = *(const float4*)&Bs[k][tn0];
            *(float4*)(b + 4) = *(const float4*)&Bs[k][tn0 + 64];
#pragma unroll
            for (int i = 0; i < 8; i++)
#pragma unroll
                for (int j = 0; j < 8; j++)
                    acc[i][j] += a[i] * b[j];
        }
    }

#pragma unroll
    for (int i = 0; i < 8; i++) {
        int m = mb + ((i < 4) ? (tm0 + i) : (tm0 + 64 + i - 4));
        float* out = d_S + (size_t)m * N_TOT + nb;
        *(float4*)(out + tn0)      = make_float4(acc[i][0], acc[i][1], acc[i][2], acc[i][3]);
        *(float4*)(out + tn0 + 64) = make_float4(acc[i][4], acc[i][5], acc[i][6], acc[i][7]);
    }
}

// ---------------------------------------------------------------------------
// Gram kernels: G = X Xᵀ for each item (R rows of length DIM).
// One CTA per item. sel: 0 -> d_Gi (R=36), 1 -> d_Gc (R=32)
// ---------------------------------------------------------------------------
__global__ __launch_bounds__(256)
void gram_kernel(const float* __restrict__ X, int R, int sel) {
    __shared__ float buf[36][129];
    const float* Xi = X + (size_t)blockIdx.x * R * DIM;
    const int npairs = R * R;              // <= 1296
    float acc[6];
#pragma unroll
    for (int j = 0; j < 6; j++) acc[j] = 0.f;

    for (int k0 = 0; k0 < DIM; k0 += 128) {
        __syncthreads();
        for (int idx = threadIdx.x; idx < R * 128; idx += blockDim.x) {
            int r = idx >> 7, kk = idx & 127;
            buf[r][kk] = Xi[(size_t)r * DIM + k0 + kk];
        }
        __syncthreads();
        int j = 0;
        for (int p = threadIdx.x; p < npairs; p += blockDim.x, j++) {
            int r = p / R, r2 = p - r * R;
            float s = 0.f;
#pragma unroll 8
            for (int kk = 0; kk < 128; kk++)
                s += buf[r][kk] * buf[r2][kk];
            acc[j] += s;
        }
    }
    float* G = (sel == 0 ? d_Gi : d_Gc) + (size_t)blockIdx.x * npairs;
    int j = 0;
    for (int p = threadIdx.x; p < npairs; p += blockDim.x, j++)
        G[p] = acc[j];
}

// ---------------------------------------------------------------------------
// Stage 2: per-(image,caption) pair focal attention both directions.
// Grid (N_IMG, N_CAP), 128 threads. warp0: t2i (32 words). warps2-3: i2t (36 regions).
// ---------------------------------------------------------------------------
__global__ __launch_bounds__(128)
void attn_kernel(float* __restrict__ out) {
    const int i = blockIdx.x;
    const int c = blockIdx.y;
    const int tid = threadIdx.x;

    __shared__ float Ss[36][33];
    __shared__ float Gi[36][37];
    __shared__ float Gc[32][33];
    __shared__ float rn_t[36];   // per-region norm over words of lrelu(S)
    __shared__ float rn_i[32];   // per-word   norm over regions of lrelu(S)
    __shared__ float red[128];

    const float* Sblk = d_S + (size_t)(i * N_REG) * N_TOT + c * N_WORD;
    for (int idx = tid; idx < 36 * 32; idx += 128) {
        int r = idx >> 5, w = idx & 31;
        Ss[r][w] = Sblk[(size_t)r * N_TOT + w];
    }
    const float* gi = d_Gi + (size_t)i * (36 * 36);
    for (int idx = tid; idx < 36 * 36; idx += 128)
        Gi[idx / 36][idx % 36] = gi[idx];
    const float* gc = d_Gc + (size_t)c * (32 * 32);
    for (int idx = tid; idx < 32 * 32; idx += 128)
        Gc[idx >> 5][idx & 31] = gc[idx];
    __syncthreads();

    if (tid < 36) {
        float s = 0.f;
#pragma unroll
        for (int w = 0; w < 32; w++) { float v = lrelu(Ss[tid][w]); s += v * v; }
        rn_t[tid] = sqrtf(s);
    } else if (tid >= 64 && tid < 96) {
        int w = tid - 64;
        float s = 0.f;
#pragma unroll
        for (int r = 0; r < 36; r++) { float v = lrelu(Ss[r][w]); s += v * v; }
        rn_i[w] = sqrtf(s);
    }
    __syncthreads();

    float myval = 0.f;

    if (tid < 32) {
        // ---- t2i: query = word w, context = 36 regions ----
        const int w = tid;
        float a[36];
        float mx = -1e30f;
#pragma unroll
        for (int r = 0; r < 36; r++) {
            float v = lrelu(Ss[r][w]) / (rn_t[r] + EPSV);
            a[r] = v;
            mx = fmaxf(mx, v);
        }
        float esum = 0.f;
#pragma unroll
        for (int r = 0; r < 36; r++) { float e = __expf(LAMBDA * (a[r] - mx)); a[r] = e; esum += e; }
        // focal mask: softmax value > mean (= 1/36)  <=>  e > esum/36
        float thresh = esum * (1.f / 36.f);
        float tsum = 0.f;
#pragma unroll
        for (int r = 0; r < 36; r++) { float v = (a[r] > thresh) ? a[r] : 0.f; a[r] = v; tsum += v; }
        float inv = 1.f / tsum;
        float num = 0.f;
#pragma unroll
        for (int r = 0; r < 36; r++) { a[r] *= inv; num += a[r] * Ss[r][w]; }
        float den2 = 0.f;
#pragma unroll
        for (int r = 0; r < 36; r++) {
            float s = 0.f;
#pragma unroll
            for (int r2 = 0; r2 < 36; r2++) s += Gi[r][r2] * a[r2];
            den2 += a[r] * s;
        }
        float ncap = fmaxf(sqrtf(Gc[w][w]), EPSV);
        float nw   = fmaxf(sqrtf(den2), EPSV);
        myval = num / (ncap * nw) * (1.f / 32.f);
    } else if (tid >= 64 && tid < 100) {
        // ---- i2t: query = region r, context = 32 words ----
        const int r = tid - 64;
        float a[32];
        float mx = -1e30f;
#pragma unroll
        for (int w = 0; w < 32; w++) {
            float v = lrelu(Ss[r][w]) / (rn_i[w] + EPSV);
            a[w] = v;
            mx = fmaxf(mx, v);
        }
        float esum = 0.f;
#pragma unroll
        for (int w = 0; w < 32; w++) { float e = __expf(LAMBDA * (a[w] - mx)); a[w] = e; esum += e; }
        float thresh = esum * (1.f / 32.f);
        float tsum = 0.f;
#pragma unroll
        for (int w = 0; w < 32; w++) { float v = (a[w] > thresh) ? a[w] : 0.f; a[w] = v; tsum += v; }
        float inv = 1.f / tsum;
        float num = 0.f;
#pragma unroll
        for (int w = 0; w < 32; w++) { a[w] *= inv; num += a[w] * Ss[r][w]; }
        float den2 = 0.f;
#pragma unroll
        for (int w = 0; w < 32; w++) {
            float s = 0.f;
#pragma unroll
            for (int w2 = 0; w2 < 32; w2++) s += Gc[w][w2] * a[w2];
            den2 += a[w] * s;
        }
        float nimg = fmaxf(sqrtf(Gi[r][r]), EPSV);
        float nw   = fmaxf(sqrtf(den2), EPSV);
        myval = num / (nimg * nw) * (1.f / 36.f);
    }

    red[tid] = myval;
    __syncthreads();
#pragma unroll
    for (int s = 64; s > 0; s >>= 1) {
        if (tid < s) red[tid] += red[tid + s];
        __syncthreads();
    }
    if (tid == 0) out[i * N_CAP + c] = red[0];
}

// ---------------------------------------------------------------------------
extern "C" void kernel_launch(void* const* d_in, const int* in_sizes, int n_in,
                              void* d_out, int out_size) {
    const float* images   = (const float*)d_in[0];   // (128,36,1024)
    const float* captions = (const float*)d_in[1];   // (128,32,1024)
    // d_in[2] cap_lens unused (all == 32)
    float* out = (float*)d_out;                       // (128,128) = (n_image, n_caption)

    dim3 ggrid(32, 36);  // (n-tiles, m-tiles)
    sgemm_kernel<<<ggrid, 256>>>(images, captions);
    gram_kernel<<<N_IMG, 256>>>(images, N_REG, 0);
    gram_kernel<<<N_CAP, 256>>>(captions, N_WORD, 1);
    dim3 agrid(N_IMG, N_CAP);
    attn_kernel<<<agrid, 128>>>(out);
}

// round 3
// speedup vs baseline: 1.3090x; 1.3090x over previous
#include <cuda_runtime.h>
#include <cuda_bf16.h>
#include <math.h>
#include <stdint.h>

#define N_IMG  128
#define N_REG  36
#define N_CAP  128
#define N_WORD 32
#define DIM    1024
#define LAMBDA 20.0f
#define EPSV   1e-8f
#define SLOPE  0.1f

#define M_TOT 4608              // 128*36
#define N_TOT 4096              // 128*32
#define KCAT  3072              // 3 * 1024 (hi/lo concat)
#define KB    (KCAT * 2)        // 6144 bytes per row
#define NK    96                // KCAT / 32

// ---------------- scratch (static; no cudaMalloc allowed) ----------------
__device__ __align__(256) float         d_S[(size_t)M_TOT * N_TOT];     // 75.5MB
__device__ __align__(256) __nv_bfloat16 d_Acat[(size_t)M_TOT * KCAT];   // [Ah|Ah|Al]
__device__ __align__(256) __nv_bfloat16 d_Bcat[(size_t)N_TOT * KCAT];   // [Bh|Bl|Bh]
__device__ __align__(256) float d_Gi[N_IMG * N_REG * N_REG];
__device__ __align__(256) float d_Gc[N_CAP * N_WORD * N_WORD];

__device__ __forceinline__ float lrelu(float x) { return x > 0.f ? x : SLOPE * x; }

__device__ __forceinline__ uint32_t smem_u32(const void* p) {
    uint32_t a;
    asm("{ .reg .u64 t; cvta.to.shared.u64 t, %1; cvt.u32.u64 %0, t; }" : "=r"(a) : "l"(p));
    return a;
}

#define LDSM4(r0, r1, r2, r3, addr) \
    asm volatile("ldmatrix.sync.aligned.m8n8.x4.shared.b16 {%0,%1,%2,%3}, [%4];" \
        : "=r"(r0), "=r"(r1), "=r"(r2), "=r"(r3) : "r"(addr))

#define MMA16816(d, a, b) \
    asm volatile("mma.sync.aligned.m16n8k16.row.col.f32.bf16.bf16.f32 " \
        "{%0,%1,%2,%3}, {%4,%5,%6,%7}, {%8,%9}, {%0,%1,%2,%3};" \
        : "+f"((d)[0]), "+f"((d)[1]), "+f"((d)[2]), "+f"((d)[3]) \
        : "r"((a)[0]), "r"((a)[1]), "r"((a)[2]), "r"((a)[3]), "r"((b)[0]), "r"((b)[1]))

#define CP16(dst, src) \
    asm volatile("cp.async.cg.shared.global [%0], [%1], 16;" :: "r"(dst), "l"(src))

// ---------------------------------------------------------------------------
// prep: fp32 -> bf16 hi/lo concat.  sel=0: A -> d_Acat [h|h|l]; sel=1: B -> [h|l|h]
// ---------------------------------------------------------------------------
__global__ void prep_kernel(const float* __restrict__ X, int total, int sel) {
    int idx = blockIdx.x * blockDim.x + threadIdx.x;
    if (idx >= total) return;
    float a = X[idx];
    __nv_bfloat16 h = __float2bfloat16(a);
    __nv_bfloat16 l = __float2bfloat16(a - __bfloat162float(h));
    int row = idx >> 10, k = idx & 1023;
    __nv_bfloat16* out = sel ? d_Bcat : d_Acat;
    size_t base = (size_t)row * KCAT + k;
    out[base] = h;
    out[base + 1024] = sel ? l : h;
    out[base + 2048] = sel ? h : l;
}

// ---------------------------------------------------------------------------
// bf16 mma.sync GEMM: S = Acat @ Bcat^T, fp32 accum.
// CTA 128x128, BK=32, 3-stage cp.async, 8 warps (4m x 2n), warp tile 32x64.
// smem rows padded to 80B for conflict-free ldmatrix.
// ---------------------------------------------------------------------------
#define GSTAGE 20480            // 10KB A + 10KB B per stage
#define GEMM_SMEM (3 * GSTAGE)  // 61440

__global__ __launch_bounds__(256, 2)
void gemm_kernel() {
    extern __shared__ char smem[];
    const uint32_t sb = smem_u32(smem);
    const int tid  = threadIdx.x;
    const int lane = tid & 31;
    const int wid  = tid >> 5;
    const int wm   = wid & 3;          // 0..3 -> m offset *32
    const int wn   = wid >> 2;         // 0..1 -> n offset *64
    const int mb   = blockIdx.y * 128;
    const int nb   = blockIdx.x * 128;

    const char* Ag = (const char*)d_Acat + (size_t)mb * KB;
    const char* Bg = (const char*)d_Bcat + (size_t)nb * KB;

    float acc[2][8][4];
#pragma unroll
    for (int i = 0; i < 2; i++)
#pragma unroll
        for (int j = 0; j < 8; j++)
#pragma unroll
            for (int q = 0; q < 4; q++) acc[i][j][q] = 0.f;

    // stage loader: 128 rows x 4 chunks(16B) each of A and B
    auto load_stage = [&](int s, int kt) {
        const uint32_t sA = sb + s * GSTAGE;
        const uint32_t sB = sA + 10240;
        const char* Asrc = Ag + kt * 64;
        const char* Bsrc = Bg + kt * 64;
#pragma unroll
        for (int i = 0; i < 2; i++) {
            int idx = tid + i * 256;
            int row = idx >> 2, seg = idx & 3;
            CP16(sA + row * 80 + seg * 16, Asrc + (size_t)row * KB + seg * 16);
        }
#pragma unroll
        for (int i = 0; i < 2; i++) {
            int idx = tid + i * 256;
            int row = idx >> 2, seg = idx & 3;
            CP16(sB + row * 80 + seg * 16, Bsrc + (size_t)row * KB + seg * 16);
        }
    };

    load_stage(0, 0);
    asm volatile("cp.async.commit_group;" ::: "memory");
    load_stage(1, 1);
    asm volatile("cp.async.commit_group;" ::: "memory");

    // precomputed intra-stage ldmatrix offsets
    const uint32_t aoff = (uint32_t)((wm * 32 + (lane & 15)) * 80 + (lane >> 4) * 16);
    const uint32_t boff = (uint32_t)((wn * 64 + (lane & 7) + ((lane >> 4) & 1) * 8) * 80
                                     + ((lane >> 3) & 1) * 16);

    for (int kt = 0; kt < NK; kt++) {
        const int s = kt - (kt / 3) * 3;
        asm volatile("cp.async.wait_group 1;" ::: "memory");
        __syncthreads();
        if (kt + 2 < NK) {
            int s2 = (kt + 2) - ((kt + 2) / 3) * 3;
            load_stage(s2, kt + 2);
        }
        asm volatile("cp.async.commit_group;" ::: "memory");

        const uint32_t sA = sb + s * GSTAGE;
        const uint32_t sB = sA + 10240;
#pragma unroll
        for (int ks = 0; ks < 2; ks++) {
            uint32_t a[2][4];
#pragma unroll
            for (int mi = 0; mi < 2; mi++)
                LDSM4(a[mi][0], a[mi][1], a[mi][2], a[mi][3],
                      sA + aoff + mi * (16 * 80) + ks * 32);
            uint32_t b[8][2];
#pragma unroll
            for (int nt = 0; nt < 4; nt++) {
                uint32_t r0, r1, r2, r3;
                LDSM4(r0, r1, r2, r3, sB + boff + nt * (16 * 80) + ks * 32);
                b[2 * nt][0] = r0; b[2 * nt][1] = r1;
                b[2 * nt + 1][0] = r2; b[2 * nt + 1][1] = r3;
            }
#pragma unroll
            for (int mi = 0; mi < 2; mi++)
#pragma unroll
                for (int nj = 0; nj < 8; nj++)
                    MMA16816(acc[mi][nj], a[mi], b[nj]);
        }
        __syncthreads();
    }
    asm volatile("cp.async.wait_group 0;" ::: "memory");

    // epilogue: direct fp32 stores
#pragma unroll
    for (int mi = 0; mi < 2; mi++) {
#pragma unroll
        for (int nj = 0; nj < 8; nj++) {
            int row = mb + wm * 32 + mi * 16 + (lane >> 2);
            int col = nb + wn * 64 + nj * 8 + (lane & 3) * 2;
            float* p0 = d_S + (size_t)row * N_TOT + col;
            float* p1 = d_S + (size_t)(row + 8) * N_TOT + col;
            *(float2*)p0 = make_float2(acc[mi][nj][0], acc[mi][nj][1]);
            *(float2*)p1 = make_float2(acc[mi][nj][2], acc[mi][nj][3]);
        }
    }
}

// ---------------------------------------------------------------------------
// Gram kernels: G = X X^T per item
// ---------------------------------------------------------------------------
__global__ __launch_bounds__(256)
void gram_kernel(const float* __restrict__ X, int R, int sel) {
    __shared__ float buf[36][129];
    const float* Xi = X + (size_t)blockIdx.x * R * DIM;
    const int npairs = R * R;
    float acc[6];
#pragma unroll
    for (int j = 0; j < 6; j++) acc[j] = 0.f;

    for (int k0 = 0; k0 < DIM; k0 += 128) {
        __syncthreads();
        for (int idx = threadIdx.x; idx < R * 128; idx += blockDim.x) {
            int r = idx >> 7, kk = idx & 127;
            buf[r][kk] = Xi[(size_t)r * DIM + k0 + kk];
        }
        __syncthreads();
        int j = 0;
        for (int p = threadIdx.x; p < npairs; p += blockDim.x, j++) {
            int r = p / R, r2 = p - r * R;
            float s = 0.f;
#pragma unroll 8
            for (int kk = 0; kk < 128; kk++) s += buf[r][kk] * buf[r2][kk];
            acc[j] += s;
        }
    }
    float* G = (sel == 0 ? d_Gi : d_Gc) + (size_t)blockIdx.x * npairs;
    int j = 0;
    for (int p = threadIdx.x; p < npairs; p += blockDim.x, j++) G[p] = acc[j];
}

// ---------------------------------------------------------------------------
// attention: one CTA per (image, caption)
// ---------------------------------------------------------------------------
__global__ __launch_bounds__(128, 8)
void attn_kernel(float* __restrict__ out) {
    const int i = blockIdx.x, c = blockIdx.y, tid = threadIdx.x;

    __shared__ float Ss[36][33];
    __shared__ float Gi[36][37];
    __shared__ float Gc[32][33];
    __shared__ float Wt[32][37];   // t2i weights: [word][region]
    __shared__ float Wi[36][33];   // i2t weights: [region][word]
    __shared__ float rn_t[36], rn_i[32];
    __shared__ float den_t[32], den_i[36];
    __shared__ float num_t[32], num_i[36];
    __shared__ float red[128];

    const float* Sblk = d_S + (size_t)(i * N_REG) * N_TOT + c * N_WORD;
    for (int idx = tid; idx < 36 * 32; idx += 128) {
        int r = idx >> 5, w = idx & 31;
        Ss[r][w] = Sblk[(size_t)r * N_TOT + w];
    }
    const float* gi = d_Gi + (size_t)i * (36 * 36);
    for (int idx = tid; idx < 36 * 36; idx += 128) Gi[idx / 36][idx % 36] = gi[idx];
    const float* gc = d_Gc + (size_t)c * (32 * 32);
    for (int idx = tid; idx < 32 * 32; idx += 128) Gc[idx >> 5][idx & 31] = gc[idx];
    if (tid < 32) den_t[tid] = 0.f;
    if (tid < 36) den_i[tid] = 0.f;
    __syncthreads();

    if (tid < 36) {
        float s = 0.f;
#pragma unroll
        for (int w = 0; w < 32; w++) { float v = lrelu(Ss[tid][w]); s += v * v; }
        rn_t[tid] = sqrtf(s) + EPSV;
    } else if (tid >= 64 && tid < 96) {
        int w = tid - 64;
        float s = 0.f;
#pragma unroll
        for (int r = 0; r < 36; r++) { float v = lrelu(Ss[r][w]); s += v * v; }
        rn_i[w] = sqrtf(s) + EPSV;
    }
    __syncthreads();

    if (tid < 32) {
        const int w = tid;
        float mx = -1e30f;
#pragma unroll
        for (int r = 0; r < 36; r++) {
            float v = lrelu(Ss[r][w]) / rn_t[r];
            Wt[w][r] = v; mx = fmaxf(mx, v);
        }
        float esum = 0.f;
#pragma unroll
        for (int r = 0; r < 36; r++) {
            float e = __expf(LAMBDA * (Wt[w][r] - mx));
            Wt[w][r] = e; esum += e;
        }
        float th = esum * (1.f / 36.f), tsum = 0.f;
#pragma unroll
        for (int r = 0; r < 36; r++) {
            float v = Wt[w][r]; v = (v > th) ? v : 0.f;
            Wt[w][r] = v; tsum += v;
        }
        float inv = 1.f / tsum, num = 0.f;
#pragma unroll
        for (int r = 0; r < 36; r++) {
            float a = Wt[w][r] * inv;
            Wt[w][r] = a; num += a * Ss[r][w];
        }
        num_t[w] = num;
    } else if (tid >= 64 && tid < 100) {
        const int r = tid - 64;
        float mx = -1e30f;
#pragma unroll
        for (int w = 0; w < 32; w++) {
            float v = lrelu(Ss[r][w]) / rn_i[w];
            Wi[r][w] = v; mx = fmaxf(mx, v);
        }
        float esum = 0.f;
#pragma unroll
        for (int w = 0; w < 32; w++) {
            float e = __expf(LAMBDA * (Wi[r][w] - mx));
            Wi[r][w] = e; esum += e;
        }
        float th = esum * (1.f / 32.f), tsum = 0.f;
#pragma unroll
        for (int w = 0; w < 32; w++) {
            float v = Wi[r][w]; v = (v > th) ? v : 0.f;
            Wi[r][w] = v; tsum += v;
        }
        float inv = 1.f / tsum, num = 0.f;
#pragma unroll
        for (int w = 0; w < 32; w++) {
            float a = Wi[r][w] * inv;
            Wi[r][w] = a; num += a * Ss[r][w];
        }
        num_i[r] = num;
    }
    __syncthreads();

    // quadratic forms den = a^T G a, parallel over 128 threads
#pragma unroll
    for (int j = 0; j < 9; j++) {                  // t2i: 36*32 elements
        int idx = tid + j * 128;
        int r2 = idx >> 5, w = idx & 31;
        float p = 0.f;
#pragma unroll
        for (int r = 0; r < 36; r++) p += Wt[w][r] * Gi[r][r2];
        atomicAdd(&den_t[w], p * Wt[w][r2]);
    }
#pragma unroll
    for (int j = 0; j < 9; j++) {                  // i2t: 32*36 elements
        int idx = tid + j * 128;
        int w2 = idx / 36, r = idx - w2 * 36;
        float p = 0.f;
#pragma unroll
        for (int w = 0; w < 32; w++) p += Wi[r][w] * Gc[w][w2];
        atomicAdd(&den_i[r], p * Wi[r][w2]);
    }
    __syncthreads();

    float myval = 0.f;
    if (tid < 32) {
        int w = tid;
        myval = num_t[w] / (fmaxf(sqrtf(Gc[w][w]), EPSV) * fmaxf(sqrtf(den_t[w]), EPSV)) * (1.f / 32.f);
    } else if (tid >= 64 && tid < 100) {
        int r = tid - 64;
        myval = num_i[r] / (fmaxf(sqrtf(Gi[r][r]), EPSV) * fmaxf(sqrtf(den_i[r]), EPSV)) * (1.f / 36.f);
    }
    red[tid] = myval;
    __syncthreads();
#pragma unroll
    for (int s = 64; s > 0; s >>= 1) {
        if (tid < s) red[tid] += red[tid + s];
        __syncthreads();
    }
    if (tid == 0) out[i * N_CAP + c] = red[0];
}

// ---------------------------------------------------------------------------
extern "C" void kernel_launch(void* const* d_in, const int* in_sizes, int n_in,
                              void* d_out, int out_size) {
    const float* images   = (const float*)d_in[0];   // (128,36,1024)
    const float* captions = (const float*)d_in[1];   // (128,32,1024)
    float* out = (float*)d_out;                       // (128,128)

    prep_kernel<<<(M_TOT * DIM) / 256, 256>>>(images, M_TOT * DIM, 0);
    prep_kernel<<<(N_TOT * DIM) / 256, 256>>>(captions, N_TOT * DIM, 1);
    gram_kernel<<<N_IMG, 256>>>(images, N_REG, 0);
    gram_kernel<<<N_CAP, 256>>>(captions, N_WORD, 1);

    cudaFuncSetAttribute(gemm_kernel, cudaFuncAttributeMaxDynamicSharedMemorySize, GEMM_SMEM);
    dim3 ggrid(N_TOT / 128, M_TOT / 128);   // (32, 36)
    gemm_kernel<<<ggrid, 256, GEMM_SMEM>>>();

    dim3 agrid(N_IMG, N_CAP);
    attn_kernel<<<agrid, 128>>>(out);
}

// round 4
// speedup vs baseline: 1.5266x; 1.1662x over previous
#include <cuda_runtime.h>
#include <cuda_bf16.h>
#include <math.h>
#include <stdint.h>

#define N_IMG  128
#define N_REG  36
#define N_CAP  128
#define N_WORD 32
#define DIM    1024
#define LAMBDA 20.0f
#define EPSV   1e-8f
#define SLOPE  0.1f

#define M_TOT 4608              // 128*36
#define N_TOT 4096              // 128*32
#define KCAT  3072              // 3 * 1024 (hi/lo concat)
#define KB    (KCAT * 2)        // 6144 bytes per row
#define NK2   48                // KCAT / 64

// ---------------- scratch (static; no cudaMalloc allowed) ----------------
__device__ __align__(256) float         d_S[(size_t)M_TOT * N_TOT];     // 75.5MB
__device__ __align__(256) __nv_bfloat16 d_Acat[(size_t)M_TOT * KCAT];   // [Ah|Ah|Al]
__device__ __align__(256) __nv_bfloat16 d_Bcat[(size_t)N_TOT * KCAT];   // [Bh|Bl|Bh]
__device__ __align__(256) float d_Gi[N_IMG * N_REG * N_REG];
__device__ __align__(256) float d_Gc[N_CAP * N_WORD * N_WORD];

__device__ __forceinline__ float lrelu(float x) { return x > 0.f ? x : SLOPE * x; }

__device__ __forceinline__ uint32_t smem_u32(const void* p) {
    uint32_t a;
    asm("{ .reg .u64 t; cvta.to.shared.u64 t, %1; cvt.u32.u64 %0, t; }" : "=r"(a) : "l"(p));
    return a;
}

#define LDSM4(r0, r1, r2, r3, addr) \
    asm volatile("ldmatrix.sync.aligned.m8n8.x4.shared.b16 {%0,%1,%2,%3}, [%4];" \
        : "=r"(r0), "=r"(r1), "=r"(r2), "=r"(r3) : "r"(addr))

#define MMA16816(d, a, b) \
    asm volatile("mma.sync.aligned.m16n8k16.row.col.f32.bf16.bf16.f32 " \
        "{%0,%1,%2,%3}, {%4,%5,%6,%7}, {%8,%9}, {%0,%1,%2,%3};" \
        : "+f"((d)[0]), "+f"((d)[1]), "+f"((d)[2]), "+f"((d)[3]) \
        : "r"((a)[0]), "r"((a)[1]), "r"((a)[2]), "r"((a)[3]), "r"((b)[0]), "r"((b)[1]))

#define CP16(dst, src) \
    asm volatile("cp.async.cg.shared.global [%0], [%1], 16;" :: "r"(dst), "l"(src))

// ---------------------------------------------------------------------------
// prep: fp32 -> bf16 hi/lo concat.  sel=0: A -> d_Acat [h|h|l]; sel=1: B -> [h|l|h]
// ---------------------------------------------------------------------------
__global__ void prep_kernel(const float* __restrict__ X, int total, int sel) {
    int idx = blockIdx.x * blockDim.x + threadIdx.x;
    if (idx >= total) return;
    float a = X[idx];
    __nv_bfloat16 h = __float2bfloat16(a);
    __nv_bfloat16 l = __float2bfloat16(a - __bfloat162float(h));
    int row = idx >> 10, k = idx & 1023;
    __nv_bfloat16* out = sel ? d_Bcat : d_Acat;
    size_t base = (size_t)row * KCAT + k;
    out[base] = h;
    out[base + 1024] = sel ? l : h;
    out[base + 2048] = sel ? h : l;
}

// ---------------------------------------------------------------------------
// bf16 mma.sync GEMM: S = Acat @ Bcat^T, fp32 accum.
// CTA 128x256, BK=64, 3-stage cp.async, 8 warps (2m x 4n), warp tile 64x64.
// smem rows padded to 144B for conflict-free ldmatrix.
// ---------------------------------------------------------------------------
#define APITCH 144
#define ASTAGE (128 * APITCH)          // 18432
#define BSTAGE (256 * APITCH)          // 36864
#define GSTAGE (ASTAGE + BSTAGE)       // 55296
#define GEMM_SMEM (3 * GSTAGE)         // 165888

__global__ __launch_bounds__(256, 1)
void gemm_kernel() {
    extern __shared__ char smem[];
    const uint32_t sb = smem_u32(smem);
    const int tid  = threadIdx.x;
    const int lane = tid & 31;
    const int wid  = tid >> 5;
    const int wm   = wid & 1;          // 0..1 -> m offset *64
    const int wn   = wid >> 1;         // 0..3 -> n offset *64
    const int mb   = blockIdx.y * 128;
    const int nb   = blockIdx.x * 256;

    const char* Ag = (const char*)d_Acat + (size_t)mb * KB;
    const char* Bg = (const char*)d_Bcat + (size_t)nb * KB;

    float acc[4][8][4];
#pragma unroll
    for (int i = 0; i < 4; i++)
#pragma unroll
        for (int j = 0; j < 8; j++)
#pragma unroll
            for (int q = 0; q < 4; q++) acc[i][j][q] = 0.f;

    // stage loader: A 128 rows x 8x16B, B 256 rows x 8x16B
    auto load_stage = [&](int s, int kt) {
        const uint32_t sA = sb + s * GSTAGE;
        const uint32_t sB = sA + ASTAGE;
        const char* Asrc = Ag + kt * 128;
        const char* Bsrc = Bg + kt * 128;
#pragma unroll
        for (int i = 0; i < 4; i++) {
            int idx = tid + i * 256;
            int row = idx >> 3, seg = idx & 7;
            CP16(sA + row * APITCH + seg * 16, Asrc + (size_t)row * KB + seg * 16);
        }
#pragma unroll
        for (int i = 0; i < 8; i++) {
            int idx = tid + i * 256;
            int row = idx >> 3, seg = idx & 7;
            CP16(sB + row * APITCH + seg * 16, Bsrc + (size_t)row * KB + seg * 16);
        }
    };

    load_stage(0, 0);
    asm volatile("cp.async.commit_group;" ::: "memory");
    load_stage(1, 1);
    asm volatile("cp.async.commit_group;" ::: "memory");

    const uint32_t aoff = (uint32_t)((wm * 64 + (lane & 15)) * APITCH + (lane >> 4) * 16);
    const uint32_t boff = (uint32_t)((wn * 64 + (lane & 7) + ((lane >> 4) & 1) * 8) * APITCH
                                     + ((lane >> 3) & 1) * 16);

    for (int kt = 0; kt < NK2; kt++) {
        const int s = kt % 3;
        asm volatile("cp.async.wait_group 1;" ::: "memory");
        __syncthreads();
        if (kt + 2 < NK2) load_stage((kt + 2) % 3, kt + 2);
        asm volatile("cp.async.commit_group;" ::: "memory");

        const uint32_t sA = sb + s * GSTAGE;
        const uint32_t sB = sA + ASTAGE;
#pragma unroll
        for (int ks = 0; ks < 4; ks++) {
            const uint32_t kbyte = ks * 32;
            uint32_t a[4][4];
#pragma unroll
            for (int mi = 0; mi < 4; mi++)
                LDSM4(a[mi][0], a[mi][1], a[mi][2], a[mi][3],
                      sA + aoff + mi * (16 * APITCH) + kbyte);
            uint32_t b[8][2];
#pragma unroll
            for (int nt = 0; nt < 4; nt++) {
                uint32_t r0, r1, r2, r3;
                LDSM4(r0, r1, r2, r3, sB + boff + nt * (16 * APITCH) + kbyte);
                b[2 * nt][0] = r0; b[2 * nt][1] = r1;
                b[2 * nt + 1][0] = r2; b[2 * nt + 1][1] = r3;
            }
#pragma unroll
            for (int mi = 0; mi < 4; mi++)
#pragma unroll
                for (int nj = 0; nj < 8; nj++)
                    MMA16816(acc[mi][nj], a[mi], b[nj]);
        }
        __syncthreads();
    }
    asm volatile("cp.async.wait_group 0;" ::: "memory");

    // epilogue: direct fp32 stores
#pragma unroll
    for (int mi = 0; mi < 4; mi++) {
#pragma unroll
        for (int nj = 0; nj < 8; nj++) {
            int row = mb + wm * 64 + mi * 16 + (lane >> 2);
            int col = nb + wn * 64 + nj * 8 + (lane & 3) * 2;
            float* p0 = d_S + (size_t)row * N_TOT + col;
            float* p1 = d_S + (size_t)(row + 8) * N_TOT + col;
            *(float2*)p0 = make_float2(acc[mi][nj][0], acc[mi][nj][1]);
            *(float2*)p1 = make_float2(acc[mi][nj][2], acc[mi][nj][3]);
        }
    }
}

// ---------------------------------------------------------------------------
// merged Gram kernel: grid 256 (0-127 images R=36, 128-255 captions R=32)
// 3x2 register tiling over the pair matrix, BK=64 smem chunks
// ---------------------------------------------------------------------------
__global__ __launch_bounds__(256)
void gram2_kernel(const float* __restrict__ imgs, const float* __restrict__ caps) {
    const int item = blockIdx.x;
    const bool isCap = item >= N_IMG;
    const float* X = isCap ? caps + (size_t)(item - N_IMG) * N_WORD * DIM
                           : imgs + (size_t)item * N_REG * DIM;
    const int R = isCap ? N_WORD : N_REG;

    __shared__ float xs[36][68];
    const int tid = threadIdx.x;
    const int tr = (tid % 12) * 3;
    const int tc = (tid / 12) * 2;
    const bool act = tid < 216;

    float acc00 = 0.f, acc01 = 0.f, acc10 = 0.f, acc11 = 0.f, acc20 = 0.f, acc21 = 0.f;

    for (int k0 = 0; k0 < DIM; k0 += 64) {
        __syncthreads();
        for (int idx = tid; idx < 36 * 64; idx += 256) {
            int r = idx >> 6, kk = idx & 63;
            xs[r][kk] = (r < R) ? X[(size_t)r * DIM + k0 + kk] : 0.f;
        }
        __syncthreads();
        if (act) {
#pragma unroll 8
            for (int kk = 0; kk < 64; kk++) {
                float a0 = xs[tr][kk], a1 = xs[tr + 1][kk], a2 = xs[tr + 2][kk];
                float b0 = xs[tc][kk], b1 = xs[tc + 1][kk];
                acc00 += a0 * b0; acc01 += a0 * b1;
                acc10 += a1 * b0; acc11 += a1 * b1;
                acc20 += a2 * b0; acc21 += a2 * b1;
            }
        }
    }
    if (act) {
        float* G = isCap ? d_Gc + (size_t)(item - N_IMG) * (N_WORD * N_WORD)
                         : d_Gi + (size_t)item * (N_REG * N_REG);
        float v[3][2] = {{acc00, acc01}, {acc10, acc11}, {acc20, acc21}};
#pragma unroll
        for (int i = 0; i < 3; i++)
#pragma unroll
            for (int j = 0; j < 2; j++) {
                int r = tr + i, c2 = tc + j;
                if (r < R && c2 < R) G[r * R + c2] = v[i][j];
            }
    }
}

// ---------------------------------------------------------------------------
// attention: one CTA per (image, caption)
// ---------------------------------------------------------------------------
__global__ __launch_bounds__(128, 8)
void attn_kernel(float* __restrict__ out) {
    const int i = blockIdx.x, c = blockIdx.y, tid = threadIdx.x;

    __shared__ float Ss[36][33];
    __shared__ float Gi[36][37];
    __shared__ float Gc[32][33];
    __shared__ float Wt[32][37];
    __shared__ float Wi[36][33];
    __shared__ float rn_t[36], rn_i[32];
    __shared__ float den_t[32], den_i[36];
    __shared__ float num_t[32], num_i[36];
    __shared__ float red[128];

    const float* Sblk = d_S + (size_t)(i * N_REG) * N_TOT + c * N_WORD;
    for (int idx = tid; idx < 36 * 32; idx += 128) {
        int r = idx >> 5, w = idx & 31;
        Ss[r][w] = Sblk[(size_t)r * N_TOT + w];
    }
    const float* gi = d_Gi + (size_t)i * (36 * 36);
    for (int idx = tid; idx < 36 * 36; idx += 128) Gi[idx / 36][idx % 36] = gi[idx];
    const float* gc = d_Gc + (size_t)c * (32 * 32);
    for (int idx = tid; idx < 32 * 32; idx += 128) Gc[idx >> 5][idx & 31] = gc[idx];
    if (tid < 32) den_t[tid] = 0.f;
    if (tid < 36) den_i[tid] = 0.f;
    __syncthreads();

    if (tid < 36) {
        float s = 0.f;
#pragma unroll
        for (int w = 0; w < 32; w++) { float v = lrelu(Ss[tid][w]); s += v * v; }
        rn_t[tid] = sqrtf(s) + EPSV;
    } else if (tid >= 64 && tid < 96) {
        int w = tid - 64;
        float s = 0.f;
#pragma unroll
        for (int r = 0; r < 36; r++) { float v = lrelu(Ss[r][w]); s += v * v; }
        rn_i[w] = sqrtf(s) + EPSV;
    }
    __syncthreads();

    if (tid < 32) {
        const int w = tid;
        float mx = -1e30f;
#pragma unroll
        for (int r = 0; r < 36; r++) {
            float v = lrelu(Ss[r][w]) / rn_t[r];
            Wt[w][r] = v; mx = fmaxf(mx, v);
        }
        float esum = 0.f;
#pragma unroll
        for (int r = 0; r < 36; r++) {
            float e = __expf(LAMBDA * (Wt[w][r] - mx));
            Wt[w][r] = e; esum += e;
        }
        float th = esum * (1.f / 36.f), tsum = 0.f;
#pragma unroll
        for (int r = 0; r < 36; r++) {
            float v = Wt[w][r]; v = (v > th) ? v : 0.f;
            Wt[w][r] = v; tsum += v;
        }
        float inv = 1.f / tsum, num = 0.f;
#pragma unroll
        for (int r = 0; r < 36; r++) {
            float a = Wt[w][r] * inv;
            Wt[w][r] = a; num += a * Ss[r][w];
        }
        num_t[w] = num;
    } else if (tid >= 64 && tid < 100) {
        const int r = tid - 64;
        float mx = -1e30f;
#pragma unroll
        for (int w = 0; w < 32; w++) {
            float v = lrelu(Ss[r][w]) / rn_i[w];
            Wi[r][w] = v; mx = fmaxf(mx, v);
        }
        float esum = 0.f;
#pragma unroll
        for (int w = 0; w < 32; w++) {
            float e = __expf(LAMBDA * (Wi[r][w] - mx));
            Wi[r][w] = e; esum += e;
        }
        float th = esum * (1.f / 32.f), tsum = 0.f;
#pragma unroll
        for (int w = 0; w < 32; w++) {
            float v = Wi[r][w]; v = (v > th) ? v : 0.f;
            Wi[r][w] = v; tsum += v;
        }
        float inv = 1.f / tsum, num = 0.f;
#pragma unroll
        for (int w = 0; w < 32; w++) {
            float a = Wi[r][w] * inv;
            Wi[r][w] = a; num += a * Ss[r][w];
        }
        num_i[r] = num;
    }
    __syncthreads();

#pragma unroll
    for (int j = 0; j < 9; j++) {                  // t2i: 32*36 elements
        int idx = tid + j * 128;
        int r2 = idx >> 5, w = idx & 31;
        float p = 0.f;
#pragma unroll
        for (int r = 0; r < 36; r++) p += Wt[w][r] * Gi[r][r2];
        atomicAdd(&den_t[w], p * Wt[w][r2]);
    }
#pragma unroll
    for (int j = 0; j < 9; j++) {                  // i2t: 36*32 elements
        int idx = tid + j * 128;
        int w2 = idx / 36, r = idx - w2 * 36;
        float p = 0.f;
#pragma unroll
        for (int w = 0; w < 32; w++) p += Wi[r][w] * Gc[w][w2];
        atomicAdd(&den_i[r], p * Wi[r][w2]);
    }
    __syncthreads();

    float myval = 0.f;
    if (tid < 32) {
        int w = tid;
        myval = num_t[w] / (fmaxf(sqrtf(Gc[w][w]), EPSV) * fmaxf(sqrtf(den_t[w]), EPSV)) * (1.f / 32.f);
    } else if (tid >= 64 && tid < 100) {
        int r = tid - 64;
        myval = num_i[r] / (fmaxf(sqrtf(Gi[r][r]), EPSV) * fmaxf(sqrtf(den_i[r]), EPSV)) * (1.f / 36.f);
    }
    red[tid] = myval;
    __syncthreads();
#pragma unroll
    for (int s = 64; s > 0; s >>= 1) {
        if (tid < s) red[tid] += red[tid + s];
        __syncthreads();
    }
    if (tid == 0) out[i * N_CAP + c] = red[0];
}

// ---------------------------------------------------------------------------
extern "C" void kernel_launch(void* const* d_in, const int* in_sizes, int n_in,
                              void* d_out, int out_size) {
    const float* images   = (const float*)d_in[0];   // (128,36,1024)
    const float* captions = (const float*)d_in[1];   // (128,32,1024)
    float* out = (float*)d_out;                       // (128,128)

    prep_kernel<<<(M_TOT * DIM) / 256, 256>>>(images, M_TOT * DIM, 0);
    prep_kernel<<<(N_TOT * DIM) / 256, 256>>>(captions, N_TOT * DIM, 1);
    gram2_kernel<<<256, 256>>>(images, captions);

    cudaFuncSetAttribute(gemm_kernel, cudaFuncAttributeMaxDynamicSharedMemorySize, GEMM_SMEM);
    dim3 ggrid(N_TOT / 256, M_TOT / 128);   // (16, 36)
    gemm_kernel<<<ggrid, 256, GEMM_SMEM>>>();

    dim3 agrid(N_IMG, N_CAP);
    attn_kernel<<<agrid, 128>>>(out);
}

// round 6
// speedup vs baseline: 1.6079x; 1.0532x over previous
#include <cuda_runtime.h>
#include <cuda_bf16.h>
#include <math.h>
#include <stdint.h>

#define N_IMG  128
#define N_REG  36
#define N_CAP  128
#define N_WORD 32
#define DIM    1024
#define LAMBDA 20.0f
#define EPSV   1e-8f
#define SLOPE  0.1f

#define M_TOT 4608              // 128*36
#define N_TOT 4096              // 128*32
#define KCAT  3072              // 3 * 1024 (hi/lo concat)
#define KB    (KCAT * 2)        // 6144 bytes per row
#define NK2   48                // KCAT / 64

// ---------------- scratch (static; no cudaMalloc allowed) ----------------
__device__ __align__(256) float         d_S[(size_t)M_TOT * N_TOT];     // 75.5MB
__device__ __align__(256) __nv_bfloat16 d_Acat[(size_t)M_TOT * KCAT];   // [Ah|Ah|Al]
__device__ __align__(256) __nv_bfloat16 d_Bcat[(size_t)N_TOT * KCAT];   // [Bh|Bl|Bh]
__device__ __align__(256) float d_Gi[N_IMG * N_REG * N_REG];
__device__ __align__(256) float d_Gc[N_CAP * N_WORD * N_WORD];

__device__ __forceinline__ float lrelu(float x) { return x > 0.f ? x : SLOPE * x; }

__device__ __forceinline__ uint32_t smem_u32(const void* p) {
    uint32_t a;
    asm("{ .reg .u64 t; cvta.to.shared.u64 t, %1; cvt.u32.u64 %0, t; }" : "=r"(a) : "l"(p));
    return a;
}

#define LDSM4(r0, r1, r2, r3, addr) \
    asm volatile("ldmatrix.sync.aligned.m8n8.x4.shared.b16 {%0,%1,%2,%3}, [%4];" \
        : "=r"(r0), "=r"(r1), "=r"(r2), "=r"(r3) : "r"(addr))

#define MMA16816(d, a, b) \
    asm volatile("mma.sync.aligned.m16n8k16.row.col.f32.bf16.bf16.f32 " \
        "{%0,%1,%2,%3}, {%4,%5,%6,%7}, {%8,%9}, {%0,%1,%2,%3};" \
        : "+f"((d)[0]), "+f"((d)[1]), "+f"((d)[2]), "+f"((d)[3]) \
        : "r"((a)[0]), "r"((a)[1]), "r"((a)[2]), "r"((a)[3]), "r"((b)[0]), "r"((b)[1]))

#define CP16(dst, src) \
    asm volatile("cp.async.cg.shared.global [%0], [%1], 16;" :: "r"(dst), "l"(src))

// ---------------------------------------------------------------------------
// prep: fp32 -> bf16 hi/lo concat.  sel=0: A -> d_Acat [h|h|l]; sel=1: B -> [h|l|h]
// ---------------------------------------------------------------------------
__global__ void prep_kernel(const float* __restrict__ X, int total, int sel) {
    int idx = blockIdx.x * blockDim.x + threadIdx.x;
    if (idx >= total) return;
    float a = X[idx];
    __nv_bfloat16 h = __float2bfloat16(a);
    __nv_bfloat16 l = __float2bfloat16(a - __bfloat162float(h));
    int row = idx >> 10, k = idx & 1023;
    __nv_bfloat16* out = sel ? d_Bcat : d_Acat;
    size_t base = (size_t)row * KCAT + k;
    out[base] = h;
    out[base + 1024] = sel ? l : h;
    out[base + 2048] = sel ? h : l;
}

// ---------------------------------------------------------------------------
// bf16 mma.sync GEMM: S = Acat @ Bcat^T, fp32 accum.
// CTA 128x256, BK=64, 4-stage cp.async, 8 warps (2m x 4n), warp tile 64x64.
// Fragment double-buffering across ks steps.
// ---------------------------------------------------------------------------
#define APITCH 144
#define ASTAGE (128 * APITCH)          // 18432
#define BSTAGE (256 * APITCH)          // 36864
#define GSTAGE (ASTAGE + BSTAGE)       // 55296
#define GEMM_SMEM (4 * GSTAGE)         // 221184

__global__ __launch_bounds__(256, 1)
void gemm_kernel() {
    extern __shared__ char smem[];
    const uint32_t sb = smem_u32(smem);
    const int tid  = threadIdx.x;
    const int lane = tid & 31;
    const int wid  = tid >> 5;
    const int wm   = wid & 1;
    const int wn   = wid >> 1;
    const int mb   = blockIdx.y * 128;
    const int nb   = blockIdx.x * 256;

    const char* Ag = (const char*)d_Acat + (size_t)mb * KB;
    const char* Bg = (const char*)d_Bcat + (size_t)nb * KB;

    float acc[4][8][4];
#pragma unroll
    for (int i = 0; i < 4; i++)
#pragma unroll
        for (int j = 0; j < 8; j++)
#pragma unroll
            for (int q = 0; q < 4; q++) acc[i][j][q] = 0.f;

    auto load_stage = [&](int s, int kt) {
        const uint32_t sA = sb + s * GSTAGE;
        const uint32_t sB = sA + ASTAGE;
        const char* Asrc = Ag + kt * 128;
        const char* Bsrc = Bg + kt * 128;
#pragma unroll
        for (int i = 0; i < 4; i++) {
            int idx = tid + i * 256;
            int row = idx >> 3, seg = idx & 7;
            CP16(sA + row * APITCH + seg * 16, Asrc + (size_t)row * KB + seg * 16);
        }
#pragma unroll
        for (int i = 0; i < 8; i++) {
            int idx = tid + i * 256;
            int row = idx >> 3, seg = idx & 7;
            CP16(sB + row * APITCH + seg * 16, Bsrc + (size_t)row * KB + seg * 16);
        }
    };

    load_stage(0, 0);
    asm volatile("cp.async.commit_group;" ::: "memory");
    load_stage(1, 1);
    asm volatile("cp.async.commit_group;" ::: "memory");
    load_stage(2, 2);
    asm volatile("cp.async.commit_group;" ::: "memory");

    const uint32_t aoff = (uint32_t)((wm * 64 + (lane & 15)) * APITCH + (lane >> 4) * 16);
    const uint32_t boff = (uint32_t)((wn * 64 + (lane & 7) + ((lane >> 4) & 1) * 8) * APITCH
                                     + ((lane >> 3) & 1) * 16);

    uint32_t af[2][4][4];
    uint32_t bf[2][8][2];

    auto ldsm_ks = [&](uint32_t sA, uint32_t sB, int ks, int buf) {
        const uint32_t kbyte = (uint32_t)ks * 32;
#pragma unroll
        for (int mi = 0; mi < 4; mi++)
            LDSM4(af[buf][mi][0], af[buf][mi][1], af[buf][mi][2], af[buf][mi][3],
                  sA + aoff + mi * (16 * APITCH) + kbyte);
#pragma unroll
        for (int nt = 0; nt < 4; nt++) {
            uint32_t r0, r1, r2, r3;
            LDSM4(r0, r1, r2, r3, sB + boff + nt * (16 * APITCH) + kbyte);
            bf[buf][2 * nt][0] = r0;     bf[buf][2 * nt][1] = r1;
            bf[buf][2 * nt + 1][0] = r2; bf[buf][2 * nt + 1][1] = r3;
        }
    };

    for (int kt = 0; kt < NK2; kt++) {
        const int s = kt & 3;
        asm volatile("cp.async.wait_group 2;" ::: "memory");
        __syncthreads();
        if (kt + 3 < NK2) load_stage((kt + 3) & 3, kt + 3);
        asm volatile("cp.async.commit_group;" ::: "memory");

        const uint32_t sA = sb + s * GSTAGE;
        const uint32_t sB = sA + ASTAGE;
        ldsm_ks(sA, sB, 0, 0);
#pragma unroll
        for (int ks = 0; ks < 4; ks++) {
            const int cur = ks & 1;
            if (ks < 3) ldsm_ks(sA, sB, ks + 1, cur ^ 1);
#pragma unroll
            for (int mi = 0; mi < 4; mi++)
#pragma unroll
                for (int nj = 0; nj < 8; nj++)
                    MMA16816(acc[mi][nj], af[cur][mi], bf[cur][nj]);
        }
    }
    asm volatile("cp.async.wait_group 0;" ::: "memory");

#pragma unroll
    for (int mi = 0; mi < 4; mi++) {
#pragma unroll
        for (int nj = 0; nj < 8; nj++) {
            int row = mb + wm * 64 + mi * 16 + (lane >> 2);
            int col = nb + wn * 64 + nj * 8 + (lane & 3) * 2;
            float* p0 = d_S + (size_t)row * N_TOT + col;
            float* p1 = d_S + (size_t)(row + 8) * N_TOT + col;
            *(float2*)p0 = make_float2(acc[mi][nj][0], acc[mi][nj][1]);
            *(float2*)p1 = make_float2(acc[mi][nj][2], acc[mi][nj][3]);
        }
    }
}

// ---------------------------------------------------------------------------
// merged Gram kernel
// ---------------------------------------------------------------------------
__global__ __launch_bounds__(256)
void gram2_kernel(const float* __restrict__ imgs, const float* __restrict__ caps) {
    const int item = blockIdx.x;
    const bool isCap = item >= N_IMG;
    const float* X = isCap ? caps + (size_t)(item - N_IMG) * N_WORD * DIM
                           : imgs + (size_t)item * N_REG * DIM;
    const int R = isCap ? N_WORD : N_REG;

    __shared__ float xs[36][68];
    const int tid = threadIdx.x;
    const int tr = (tid % 12) * 3;
    const int tc = (tid / 12) * 2;
    const bool act = tid < 216;

    float acc00 = 0.f, acc01 = 0.f, acc10 = 0.f, acc11 = 0.f, acc20 = 0.f, acc21 = 0.f;

    for (int k0 = 0; k0 < DIM; k0 += 64) {
        __syncthreads();
        for (int idx = tid; idx < 36 * 64; idx += 256) {
            int r = idx >> 6, kk = idx & 63;
            xs[r][kk] = (r < R) ? X[(size_t)r * DIM + k0 + kk] : 0.f;
        }
        __syncthreads();
        if (act) {
#pragma unroll 8
            for (int kk = 0; kk < 64; kk++) {
                float a0 = xs[tr][kk], a1 = xs[tr + 1][kk], a2 = xs[tr + 2][kk];
                float b0 = xs[tc][kk], b1 = xs[tc + 1][kk];
                acc00 += a0 * b0; acc01 += a0 * b1;
                acc10 += a1 * b0; acc11 += a1 * b1;
                acc20 += a2 * b0; acc21 += a2 * b1;
            }
        }
    }
    if (act) {
        float* G = isCap ? d_Gc + (size_t)(item - N_IMG) * (N_WORD * N_WORD)
                         : d_Gi + (size_t)item * (N_REG * N_REG);
        float v[3][2] = {{acc00, acc01}, {acc10, acc11}, {acc20, acc21}};
#pragma unroll
        for (int i = 0; i < 3; i++)
#pragma unroll
            for (int j = 0; j < 2; j++) {
                int r = tr + i, c2 = tc + j;
                if (r < R && c2 < R) G[r * R + c2] = v[i][j];
            }
    }
}

// ---------------------------------------------------------------------------
// attention v3b: one CTA per (image, caption), 256 threads.
// Weight phase: 2 threads per query; clamped duplicate threads write to a
// dummy shared row (fixes the round-5 cross-warp race on Wt[0]).
// ---------------------------------------------------------------------------
__global__ __launch_bounds__(256, 4)
void attn_kernel(float* __restrict__ out) {
    const int i = blockIdx.x, c = blockIdx.y, tid = threadIdx.x;

    __shared__ float Ss[36][33];
    __shared__ float Gi[36][37];
    __shared__ float Gc[32][33];
    __shared__ float Wt[32][37];    // t2i weights: [word][region]
    __shared__ float Wi[36][33];    // i2t weights: [region][word]
    __shared__ float Wd[40];        // dummy sink for clamped duplicate threads
    __shared__ float irn_t[36], irn_i[32];
    __shared__ float den_t[32], den_i[36];
    __shared__ float num_t[32], num_i[36];
    __shared__ float red[128];

    const float* Sblk = d_S + (size_t)(i * N_REG) * N_TOT + c * N_WORD;
    for (int idx = tid; idx < 36 * 32; idx += 256) {
        int r = idx >> 5, w = idx & 31;
        Ss[r][w] = Sblk[(size_t)r * N_TOT + w];
    }
    const float* gi = d_Gi + (size_t)i * (36 * 36);
    for (int idx = tid; idx < 36 * 36; idx += 256) Gi[idx / 36][idx % 36] = gi[idx];
    const float* gc = d_Gc + (size_t)c * (32 * 32);
    for (int idx = tid; idx < 32 * 32; idx += 256) Gc[idx >> 5][idx & 31] = gc[idx];
    if (tid < 32) den_t[tid] = 0.f;
    if (tid < 36) den_i[tid] = 0.f;
    __syncthreads();

    // --- norm phase: 2 threads per row/col (warps 0-4 fully active for shfl) ---
    if (tid < 160) {
        int u = tid >> 1, h = tid & 1;
        int uc = (u < 68) ? u : 0;
        float s = 0.f;
        if (uc < 36) {
            int r = uc;
#pragma unroll
            for (int j = 0; j < 16; j++) { float v = lrelu(Ss[r][h * 16 + j]); s += v * v; }
        } else {
            int w = uc - 36;
#pragma unroll
            for (int j = 0; j < 18; j++) { float v = lrelu(Ss[h * 18 + j][w]); s += v * v; }
        }
        s += __shfl_xor_sync(0xFFFFFFFFu, s, 1);
        if (u < 68 && h == 0) {
            float inv = __fdividef(1.f, sqrtf(s) + EPSV);
            if (u < 36) irn_t[u] = inv; else irn_i[u - 36] = inv;
        }
    }
    __syncthreads();

    // --- weight phase: 2 threads per query; duplicates -> dummy row ---
    if (tid < 160) {
        int q = tid >> 1, h = tid & 1;
        const bool valid = q < 68;
        int qc = valid ? q : 0;
        const bool isT2I = qc < 32;
        const int half = isT2I ? 18 : 16;
        const int base = h * half;
        const int w = isT2I ? qc : 0;
        const int r = isT2I ? 0 : qc - 32;
        float* Wrow = valid ? (isT2I ? Wt[w] : Wi[r]) : Wd;

        // pass 1: normalized lrelu values + local max
        float mx = -1e30f;
#pragma unroll 6
        for (int j = 0; j < 18; j++) {
            if (j >= half) break;
            int idx = base + j;
            float v = isT2I ? (lrelu(Ss[idx][w]) * irn_t[idx])
                            : (lrelu(Ss[r][idx]) * irn_i[idx]);
            Wrow[idx] = v;
            mx = fmaxf(mx, v);
        }
        mx = fmaxf(mx, __shfl_xor_sync(0xFFFFFFFFu, mx, 1));

        // pass 2: exp + sum
        float esum = 0.f;
#pragma unroll 6
        for (int j = 0; j < 18; j++) {
            if (j >= half) break;
            int idx = base + j;
            float e = __expf(LAMBDA * (Wrow[idx] - mx));
            Wrow[idx] = e;
            esum += e;
        }
        esum += __shfl_xor_sync(0xFFFFFFFFu, esum, 1);

        // pass 3: focal threshold (softmax > mean) + renorm sum
        float th = esum * (isT2I ? (1.f / 36.f) : (1.f / 32.f));
        float tsum = 0.f;
#pragma unroll 6
        for (int j = 0; j < 18; j++) {
            if (j >= half) break;
            int idx = base + j;
            float v = Wrow[idx];
            v = (v > th) ? v : 0.f;
            Wrow[idx] = v;
            tsum += v;
        }
        tsum += __shfl_xor_sync(0xFFFFFFFFu, tsum, 1);

        // pass 4: normalize + numerator partial
        float inv = __fdividef(1.f, tsum);
        float num = 0.f;
#pragma unroll 6
        for (int j = 0; j < 18; j++) {
            if (j >= half) break;
            int idx = base + j;
            float a = Wrow[idx] * inv;
            Wrow[idx] = a;
            num += a * (isT2I ? Ss[idx][w] : Ss[r][idx]);
        }
        num += __shfl_xor_sync(0xFFFFFFFFu, num, 1);
        if (valid && h == 0) {
            if (isT2I) num_t[w] = num; else num_i[r] = num;
        }
    }
    __syncthreads();

    // --- quadratic forms: den = a^T G a over 256 threads ---
#pragma unroll
    for (int j = 0; j < 5; j++) {                  // t2i: 1152 elements
        int idx = tid + j * 256;
        if (idx < 1152) {
            int r2 = idx >> 5, w = idx & 31;
            float p = 0.f;
#pragma unroll
            for (int r = 0; r < 36; r++) p += Wt[w][r] * Gi[r][r2];
            atomicAdd(&den_t[w], p * Wt[w][r2]);
        }
    }
#pragma unroll
    for (int j = 0; j < 5; j++) {                  // i2t: 1152 elements
        int idx = tid + j * 256;
        if (idx < 1152) {
            int w2 = idx / 36, r = idx - w2 * 36;
            float p = 0.f;
#pragma unroll
            for (int w = 0; w < 32; w++) p += Wi[r][w] * Gc[w][w2];
            atomicAdd(&den_i[r], p * Wi[r][w2]);
        }
    }
    __syncthreads();

    float myval = 0.f;
    if (tid < 32) {
        int w = tid;
        myval = num_t[w] * __fdividef(1.f,
                fmaxf(sqrtf(Gc[w][w]), EPSV) * fmaxf(sqrtf(den_t[w]), EPSV)) * (1.f / 32.f);
    } else if (tid >= 64 && tid < 100) {
        int r = tid - 64;
        myval = num_i[r] * __fdividef(1.f,
                fmaxf(sqrtf(Gi[r][r]), EPSV) * fmaxf(sqrtf(den_i[r]), EPSV)) * (1.f / 36.f);
    }
    if (tid < 128) red[tid] = myval;
    __syncthreads();
#pragma unroll
    for (int s = 64; s > 0; s >>= 1) {
        if (tid < s && tid + s < 128) red[tid] += red[tid + s];
        __syncthreads();
    }
    if (tid == 0) out[i * N_CAP + c] = red[0];
}

// ---------------------------------------------------------------------------
extern "C" void kernel_launch(void* const* d_in, const int* in_sizes, int n_in,
                              void* d_out, int out_size) {
    const float* images   = (const float*)d_in[0];   // (128,36,1024)
    const float* captions = (const float*)d_in[1];   // (128,32,1024)
    float* out = (float*)d_out;                       // (128,128)

    prep_kernel<<<(M_TOT * DIM) / 256, 256>>>(images, M_TOT * DIM, 0);
    prep_kernel<<<(N_TOT * DIM) / 256, 256>>>(captions, N_TOT * DIM, 1);
    gram2_kernel<<<256, 256>>>(images, captions);

    cudaFuncSetAttribute(gemm_kernel, cudaFuncAttributeMaxDynamicSharedMemorySize, GEMM_SMEM);
    dim3 ggrid(N_TOT / 256, M_TOT / 128);   // (16, 36)
    gemm_kernel<<<ggrid, 256, GEMM_SMEM>>>();

    dim3 agrid(N_IMG, N_CAP);
    attn_kernel<<<agrid, 256>>>(out);
}

// round 7
// speedup vs baseline: 1.8671x; 1.1612x over previous
#include <cuda_runtime.h>
#include <cuda_bf16.h>
#include <math.h>
#include <stdint.h>

#define N_IMG  128
#define N_REG  36
#define N_CAP  128
#define N_WORD 32
#define DIM    1024
#define LAMBDA 20.0f
#define EPSV   1e-8f
#define SLOPE  0.1f

#define M_TOT 4608              // 128*36
#define N_TOT 4096              // 128*32
#define KCAT  3072              // 3 * 1024 (hi/lo concat)
#define KB    (KCAT * 2)        // 6144 bytes per row
#define NK2   48                // KCAT / 64

// ---------------- scratch (static; no cudaMalloc allowed) ----------------
__device__ __align__(256) float         d_S[(size_t)M_TOT * N_TOT];     // 75.5MB
__device__ __align__(256) __nv_bfloat16 d_Acat[(size_t)M_TOT * KCAT];   // [Ah|Ah|Al]
__device__ __align__(256) __nv_bfloat16 d_Bcat[(size_t)N_TOT * KCAT];   // [Bh|Bl|Bh]
__device__ __align__(256) float d_Gi[N_IMG * N_REG * N_REG];
__device__ __align__(256) float d_Gc[N_CAP * N_WORD * N_WORD];

__device__ __forceinline__ float lrelu(float x) { return x > 0.f ? x : SLOPE * x; }

__device__ __forceinline__ uint32_t smem_u32(const void* p) {
    uint32_t a;
    asm("{ .reg .u64 t; cvta.to.shared.u64 t, %1; cvt.u32.u64 %0, t; }" : "=r"(a) : "l"(p));
    return a;
}

#define LDSM4(r0, r1, r2, r3, addr) \
    asm volatile("ldmatrix.sync.aligned.m8n8.x4.shared.b16 {%0,%1,%2,%3}, [%4];" \
        : "=r"(r0), "=r"(r1), "=r"(r2), "=r"(r3) : "r"(addr))

#define MMA16816(d, a, b) \
    asm volatile("mma.sync.aligned.m16n8k16.row.col.f32.bf16.bf16.f32 " \
        "{%0,%1,%2,%3}, {%4,%5,%6,%7}, {%8,%9}, {%0,%1,%2,%3};" \
        : "+f"((d)[0]), "+f"((d)[1]), "+f"((d)[2]), "+f"((d)[3]) \
        : "r"((a)[0]), "r"((a)[1]), "r"((a)[2]), "r"((a)[3]), "r"((b)[0]), "r"((b)[1]))

#define CP16(dst, src) \
    asm volatile("cp.async.cg.shared.global [%0], [%1], 16;" :: "r"(dst), "l"(src))

// ---------------------------------------------------------------------------
// prep: fp32 -> bf16 hi/lo concat.  sel=0: A -> d_Acat [h|h|l]; sel=1: B -> [h|l|h]
// ---------------------------------------------------------------------------
__global__ void prep_kernel(const float* __restrict__ X, int total, int sel) {
    int idx = blockIdx.x * blockDim.x + threadIdx.x;
    if (idx >= total) return;
    float a = X[idx];
    __nv_bfloat16 h = __float2bfloat16(a);
    __nv_bfloat16 l = __float2bfloat16(a - __bfloat162float(h));
    int row = idx >> 10, k = idx & 1023;
    __nv_bfloat16* out = sel ? d_Bcat : d_Acat;
    size_t base = (size_t)row * KCAT + k;
    out[base] = h;
    out[base + 1024] = sel ? l : h;
    out[base + 2048] = sel ? h : l;
}

// ---------------------------------------------------------------------------
// bf16 mma.sync GEMM: S = Acat @ Bcat^T, fp32 accum.
// CTA 128x128, BK=64, 3-stage cp.async, 4 warps (2m x 2n), warp tile 64x64.
// 2 CTAs/SM. Fragment double-buffering across ks steps.
// ---------------------------------------------------------------------------
#define APITCH 144
#define ASTAGE (128 * APITCH)          // 18432
#define GSTAGE (2 * ASTAGE)            // 36864 (A + B)
#define GEMM_SMEM (3 * GSTAGE)         // 110592

__global__ __launch_bounds__(128, 2)
void gemm_kernel() {
    extern __shared__ char smem[];
    const uint32_t sb = smem_u32(smem);
    const int tid  = threadIdx.x;
    const int lane = tid & 31;
    const int wid  = tid >> 5;
    const int wm   = wid & 1;
    const int wn   = wid >> 1;
    const int mb   = blockIdx.y * 128;
    const int nb   = blockIdx.x * 128;

    const char* Ag = (const char*)d_Acat + (size_t)mb * KB;
    const char* Bg = (const char*)d_Bcat + (size_t)nb * KB;

    float acc[4][8][4];
#pragma unroll
    for (int i = 0; i < 4; i++)
#pragma unroll
        for (int j = 0; j < 8; j++)
#pragma unroll
            for (int q = 0; q < 4; q++) acc[i][j][q] = 0.f;

    auto load_stage = [&](int s, int kt) {
        const uint32_t sA = sb + s * GSTAGE;
        const uint32_t sB = sA + ASTAGE;
        const char* Asrc = Ag + kt * 128;
        const char* Bsrc = Bg + kt * 128;
#pragma unroll
        for (int i = 0; i < 8; i++) {
            int idx = tid + i * 128;
            int row = idx >> 3, seg = idx & 7;
            CP16(sA + row * APITCH + seg * 16, Asrc + (size_t)row * KB + seg * 16);
        }
#pragma unroll
        for (int i = 0; i < 8; i++) {
            int idx = tid + i * 128;
            int row = idx >> 3, seg = idx & 7;
            CP16(sB + row * APITCH + seg * 16, Bsrc + (size_t)row * KB + seg * 16);
        }
    };

    load_stage(0, 0);
    asm volatile("cp.async.commit_group;" ::: "memory");
    load_stage(1, 1);
    asm volatile("cp.async.commit_group;" ::: "memory");

    const uint32_t aoff = (uint32_t)((wm * 64 + (lane & 15)) * APITCH + (lane >> 4) * 16);
    const uint32_t boff = (uint32_t)((wn * 64 + (lane & 7) + ((lane >> 4) & 1) * 8) * APITCH
                                     + ((lane >> 3) & 1) * 16);

    uint32_t af[2][4][4];
    uint32_t bf[2][8][2];

    auto ldsm_ks = [&](uint32_t sA, uint32_t sB, int ks, int buf) {
        const uint32_t kbyte = (uint32_t)ks * 32;
#pragma unroll
        for (int mi = 0; mi < 4; mi++)
            LDSM4(af[buf][mi][0], af[buf][mi][1], af[buf][mi][2], af[buf][mi][3],
                  sA + aoff + mi * (16 * APITCH) + kbyte);
#pragma unroll
        for (int nt = 0; nt < 4; nt++) {
            uint32_t r0, r1, r2, r3;
            LDSM4(r0, r1, r2, r3, sB + boff + nt * (16 * APITCH) + kbyte);
            bf[buf][2 * nt][0] = r0;     bf[buf][2 * nt][1] = r1;
            bf[buf][2 * nt + 1][0] = r2; bf[buf][2 * nt + 1][1] = r3;
        }
    };

    for (int kt = 0; kt < NK2; kt++) {
        const int s = kt % 3;
        asm volatile("cp.async.wait_group 1;" ::: "memory");
        __syncthreads();
        if (kt + 2 < NK2) load_stage((kt + 2) % 3, kt + 2);
        asm volatile("cp.async.commit_group;" ::: "memory");

        const uint32_t sA = sb + s * GSTAGE;
        const uint32_t sB = sA + ASTAGE;
        ldsm_ks(sA, sB, 0, 0);
#pragma unroll
        for (int ks = 0; ks < 4; ks++) {
            const int cur = ks & 1;
            if (ks < 3) ldsm_ks(sA, sB, ks + 1, cur ^ 1);
#pragma unroll
            for (int mi = 0; mi < 4; mi++)
#pragma unroll
                for (int nj = 0; nj < 8; nj++)
                    MMA16816(acc[mi][nj], af[cur][mi], bf[cur][nj]);
        }
    }
    asm volatile("cp.async.wait_group 0;" ::: "memory");

#pragma unroll
    for (int mi = 0; mi < 4; mi++) {
#pragma unroll
        for (int nj = 0; nj < 8; nj++) {
            int row = mb + wm * 64 + mi * 16 + (lane >> 2);
            int col = nb + wn * 64 + nj * 8 + (lane & 3) * 2;
            float* p0 = d_S + (size_t)row * N_TOT + col;
            float* p1 = d_S + (size_t)(row + 8) * N_TOT + col;
            *(float2*)p0 = make_float2(acc[mi][nj][0], acc[mi][nj][1]);
            *(float2*)p1 = make_float2(acc[mi][nj][2], acc[mi][nj][3]);
        }
    }
}

// ---------------------------------------------------------------------------
// merged Gram kernel
// ---------------------------------------------------------------------------
__global__ __launch_bounds__(256)
void gram2_kernel(const float* __restrict__ imgs, const float* __restrict__ caps) {
    const int item = blockIdx.x;
    const bool isCap = item >= N_IMG;
    const float* X = isCap ? caps + (size_t)(item - N_IMG) * N_WORD * DIM
                           : imgs + (size_t)item * N_REG * DIM;
    const int R = isCap ? N_WORD : N_REG;

    __shared__ float xs[36][68];
    const int tid = threadIdx.x;
    const int tr = (tid % 12) * 3;
    const int tc = (tid / 12) * 2;
    const bool act = tid < 216;

    float acc00 = 0.f, acc01 = 0.f, acc10 = 0.f, acc11 = 0.f, acc20 = 0.f, acc21 = 0.f;

    for (int k0 = 0; k0 < DIM; k0 += 64) {
        __syncthreads();
        for (int idx = tid; idx < 36 * 64; idx += 256) {
            int r = idx >> 6, kk = idx & 63;
            xs[r][kk] = (r < R) ? X[(size_t)r * DIM + k0 + kk] : 0.f;
        }
        __syncthreads();
        if (act) {
#pragma unroll 8
            for (int kk = 0; kk < 64; kk++) {
                float a0 = xs[tr][kk], a1 = xs[tr + 1][kk], a2 = xs[tr + 2][kk];
                float b0 = xs[tc][kk], b1 = xs[tc + 1][kk];
                acc00 += a0 * b0; acc01 += a0 * b1;
                acc10 += a1 * b0; acc11 += a1 * b1;
                acc20 += a2 * b0; acc21 += a2 * b1;
            }
        }
    }
    if (act) {
        float* G = isCap ? d_Gc + (size_t)(item - N_IMG) * (N_WORD * N_WORD)
                         : d_Gi + (size_t)item * (N_REG * N_REG);
        float v[3][2] = {{acc00, acc01}, {acc10, acc11}, {acc20, acc21}};
#pragma unroll
        for (int i = 0; i < 3; i++)
#pragma unroll
            for (int j = 0; j < 2; j++) {
                int r = tr + i, c2 = tc + j;
                if (r < R && c2 < R) G[r * R + c2] = v[i][j];
            }
    }
}

// ---------------------------------------------------------------------------
// attention v4: one CTA per (image, caption), 96 threads (3 warps).
// One thread per query; s[] and attention weights a[] fully register-resident.
// Quadratic forms use warp-broadcast Gram reads: 1 LDS + 1 FMA per term.
// warp0: t2i (lane = word). warp1: i2t r=0..31. warp2: i2t r=32..35 (lanes 0-3).
// ---------------------------------------------------------------------------
__global__ __launch_bounds__(96, 5)
void attn_kernel(float* __restrict__ out) {
    const int i = blockIdx.x, c = blockIdx.y, tid = threadIdx.x;

    __shared__ float Ss[36][33];
    __shared__ float Gi[36][37];
    __shared__ float Gc[32][33];
    __shared__ float irn_t[36], irn_i[32];
    __shared__ float red[3];

    const float* Sblk = d_S + (size_t)(i * N_REG) * N_TOT + c * N_WORD;
    for (int idx = tid; idx < 36 * 32; idx += 96) {
        int r = idx >> 5, w = idx & 31;
        Ss[r][w] = Sblk[(size_t)r * N_TOT + w];
    }
    const float* gi = d_Gi + (size_t)i * (36 * 36);
    for (int idx = tid; idx < 36 * 36; idx += 96) Gi[idx / 36][idx % 36] = gi[idx];
    const float* gc = d_Gc + (size_t)c * (32 * 32);
    for (int idx = tid; idx < 32 * 32; idx += 96) Gc[idx >> 5][idx & 31] = gc[idx];
    __syncthreads();

    // --- norms of lrelu(S): rows (t2i) and cols (i2t) ---
    if (tid < 36) {
        float s0 = 0.f, s1 = 0.f;
#pragma unroll
        for (int w = 0; w < 32; w += 2) {
            float v0 = lrelu(Ss[tid][w]);     s0 += v0 * v0;
            float v1 = lrelu(Ss[tid][w + 1]); s1 += v1 * v1;
        }
        irn_t[tid] = __fdividef(1.f, sqrtf(s0 + s1) + EPSV);
    } else if (tid < 68) {
        int w = tid - 36;
        float s0 = 0.f, s1 = 0.f;
#pragma unroll
        for (int r = 0; r < 36; r += 2) {
            float v0 = lrelu(Ss[r][w]);     s0 += v0 * v0;
            float v1 = lrelu(Ss[r + 1][w]); s1 += v1 * v1;
        }
        irn_i[w] = __fdividef(1.f, sqrtf(s0 + s1) + EPSV);
    }
    __syncthreads();

    const int wid = tid >> 5, lane = tid & 31;
    float val = 0.f;

    if (wid == 0) {
        // ---- t2i: query = word (lane), context = 36 regions ----
        const int w = lane;
        float s[36], a[36];
#pragma unroll
        for (int r = 0; r < 36; r++) s[r] = Ss[r][w];
        float mx = -1e30f;
#pragma unroll
        for (int r = 0; r < 36; r++) {
            float v = lrelu(s[r]) * irn_t[r];
            a[r] = v; mx = fmaxf(mx, v);
        }
        float esum = 0.f;
#pragma unroll
        for (int r = 0; r < 36; r++) { float e = __expf(LAMBDA * (a[r] - mx)); a[r] = e; esum += e; }
        float th = esum * (1.f / 36.f), tsum = 0.f;
#pragma unroll
        for (int r = 0; r < 36; r++) { float v = (a[r] > th) ? a[r] : 0.f; a[r] = v; tsum += v; }
        float inv = __fdividef(1.f, tsum), num = 0.f;
#pragma unroll
        for (int r = 0; r < 36; r++) { a[r] *= inv; num += a[r] * s[r]; }
        // quadratic form: a^T Gi a (Gi broadcast across warp)
        float den = 0.f;
#pragma unroll
        for (int r = 0; r < 36; r++) {
            float y0 = 0.f, y1 = 0.f, y2 = 0.f, y3 = 0.f;
#pragma unroll
            for (int q = 0; q < 9; q++) {
                y0 += Gi[r][4 * q + 0] * a[4 * q + 0];
                y1 += Gi[r][4 * q + 1] * a[4 * q + 1];
                y2 += Gi[r][4 * q + 2] * a[4 * q + 2];
                y3 += Gi[r][4 * q + 3] * a[4 * q + 3];
            }
            den += a[r] * ((y0 + y1) + (y2 + y3));
        }
        val = num * __fdividef(1.f,
              fmaxf(sqrtf(Gc[w][w]), EPSV) * fmaxf(sqrtf(den), EPSV));
    } else {
        // ---- i2t: query = region, context = 32 words ----
        const bool valid = (wid == 1) || (lane < 4);
        const int r = valid ? ((wid == 1) ? lane : 32 + lane) : 35;
        float s[32], a[32];
#pragma unroll
        for (int w = 0; w < 32; w++) s[w] = Ss[r][w];
        float mx = -1e30f;
#pragma unroll
        for (int w = 0; w < 32; w++) {
            float v = lrelu(s[w]) * irn_i[w];
            a[w] = v; mx = fmaxf(mx, v);
        }
        float esum = 0.f;
#pragma unroll
        for (int w = 0; w < 32; w++) { float e = __expf(LAMBDA * (a[w] - mx)); a[w] = e; esum += e; }
        float th = esum * (1.f / 32.f), tsum = 0.f;
#pragma unroll
        for (int w = 0; w < 32; w++) { float v = (a[w] > th) ? a[w] : 0.f; a[w] = v; tsum += v; }
        float inv = __fdividef(1.f, tsum), num = 0.f;
#pragma unroll
        for (int w = 0; w < 32; w++) { a[w] *= inv; num += a[w] * s[w]; }
        float den = 0.f;
#pragma unroll
        for (int w = 0; w < 32; w++) {
            float y0 = 0.f, y1 = 0.f, y2 = 0.f, y3 = 0.f;
#pragma unroll
            for (int q = 0; q < 8; q++) {
                y0 += Gc[w][4 * q + 0] * a[4 * q + 0];
                y1 += Gc[w][4 * q + 1] * a[4 * q + 1];
                y2 += Gc[w][4 * q + 2] * a[4 * q + 2];
                y3 += Gc[w][4 * q + 3] * a[4 * q + 3];
            }
            den += a[w] * ((y0 + y1) + (y2 + y3));
        }
        float v = num * __fdividef(1.f,
                  fmaxf(sqrtf(Gi[r][r]), EPSV) * fmaxf(sqrtf(den), EPSV));
        val = valid ? v : 0.f;
    }

    // warp-level sum
#pragma unroll
    for (int off = 16; off > 0; off >>= 1)
        val += __shfl_xor_sync(0xFFFFFFFFu, val, off);
    if (lane == 0) red[wid] = val;
    __syncthreads();
    if (tid == 0)
        out[i * N_CAP + c] = red[0] * (1.f / 32.f) + (red[1] + red[2]) * (1.f / 36.f);
}

// ---------------------------------------------------------------------------
extern "C" void kernel_launch(void* const* d_in, const int* in_sizes, int n_in,
                              void* d_out, int out_size) {
    const float* images   = (const float*)d_in[0];   // (128,36,1024)
    const float* captions = (const float*)d_in[1];   // (128,32,1024)
    float* out = (float*)d_out;                       // (128,128)

    prep_kernel<<<(M_TOT * DIM) / 256, 256>>>(images, M_TOT * DIM, 0);
    prep_kernel<<<(N_TOT * DIM) / 256, 256>>>(captions, N_TOT * DIM, 1);
    gram2_kernel<<<256, 256>>>(images, captions);

    cudaFuncSetAttribute(gemm_kernel, cudaFuncAttributeMaxDynamicSharedMemorySize, GEMM_SMEM);
    dim3 ggrid(N_TOT / 128, M_TOT / 128);   // (32, 36)
    gemm_kernel<<<ggrid, 128, GEMM_SMEM>>>();

    dim3 agrid(N_IMG, N_CAP);
    attn_kernel<<<agrid, 96>>>(out);
}

// round 8
// speedup vs baseline: 1.8921x; 1.0134x over previous
#include <cuda_runtime.h>
#include <cuda_bf16.h>
#include <math.h>
#include <stdint.h>

#define N_IMG  128
#define N_REG  36
#define N_CAP  128
#define N_WORD 32
#define DIM    1024
#define LAMBDA 20.0f
#define EPSV   1e-8f
#define SLOPE  0.1f

#define M_TOT 4608              // 128*36
#define N_TOT 4096              // 128*32
#define KCAT  3072              // 3 * 1024 (hi/lo concat)
#define KB    (KCAT * 2)        // 6144 bytes per row
#define NK2   48                // KCAT / 64

// ---------------- scratch (static; no cudaMalloc allowed) ----------------
__device__ __align__(256) float         d_S[(size_t)M_TOT * N_TOT];     // 75.5MB
__device__ __align__(256) __nv_bfloat16 d_Acat[(size_t)M_TOT * KCAT];   // [Ah|Ah|Al]
__device__ __align__(256) __nv_bfloat16 d_Bcat[(size_t)N_TOT * KCAT];   // [Bh|Bl|Bh]
__device__ __align__(256) float d_Gi[N_IMG * N_REG * N_REG];
__device__ __align__(256) float d_Gc[N_CAP * N_WORD * N_WORD];

__device__ __forceinline__ float lrelu(float x) { return x > 0.f ? x : SLOPE * x; }

__device__ __forceinline__ uint32_t smem_u32(const void* p) {
    uint32_t a;
    asm("{ .reg .u64 t; cvta.to.shared.u64 t, %1; cvt.u32.u64 %0, t; }" : "=r"(a) : "l"(p));
    return a;
}

#define LDSM4(r0, r1, r2, r3, addr) \
    asm volatile("ldmatrix.sync.aligned.m8n8.x4.shared.b16 {%0,%1,%2,%3}, [%4];" \
        : "=r"(r0), "=r"(r1), "=r"(r2), "=r"(r3) : "r"(addr))

#define MMA16816(d, a, b) \
    asm volatile("mma.sync.aligned.m16n8k16.row.col.f32.bf16.bf16.f32 " \
        "{%0,%1,%2,%3}, {%4,%5,%6,%7}, {%8,%9}, {%0,%1,%2,%3};" \
        : "+f"((d)[0]), "+f"((d)[1]), "+f"((d)[2]), "+f"((d)[3]) \
        : "r"((a)[0]), "r"((a)[1]), "r"((a)[2]), "r"((a)[3]), "r"((b)[0]), "r"((b)[1]))

#define CP16(dst, src) \
    asm volatile("cp.async.cg.shared.global [%0], [%1], 16;" :: "r"(dst), "l"(src))

// ---------------------------------------------------------------------------
// prep (vectorized): fp32 -> bf16 hi/lo concat, 2 elements per thread.
// sel=0: A -> d_Acat [h|h|l]; sel=1: B -> d_Bcat [h|l|h]
// ---------------------------------------------------------------------------
__global__ void prep_kernel(const float* __restrict__ X, int totalPairs, int sel) {
    int p = blockIdx.x * blockDim.x + threadIdx.x;
    if (p >= totalPairs) return;
    float2 v = *(const float2*)(X + 2 * (size_t)p);
    __nv_bfloat16 h0 = __float2bfloat16(v.x);
    __nv_bfloat16 h1 = __float2bfloat16(v.y);
    __nv_bfloat16 l0 = __float2bfloat16(v.x - __bfloat162float(h0));
    __nv_bfloat16 l1 = __float2bfloat16(v.y - __bfloat162float(h1));
    uint32_t hh = ((uint32_t)*(uint16_t*)&h1 << 16) | *(uint16_t*)&h0;
    uint32_t ll = ((uint32_t)*(uint16_t*)&l1 << 16) | *(uint16_t*)&l0;
    int row = p >> 9, kp = p & 511;       // 512 pairs per row
    uint32_t* out = (uint32_t*)(sel ? d_Bcat : d_Acat);
    size_t base = (size_t)row * (KCAT / 2) + kp;
    out[base] = hh;
    out[base + 512]  = sel ? ll : hh;
    out[base + 1024] = sel ? hh : ll;
}

// ---------------------------------------------------------------------------
// bf16 mma.sync GEMM: S = Acat @ Bcat^T, fp32 accum.
// CTA 128x128, BK=64, 3-stage cp.async, 4 warps (2m x 2n), warp tile 64x64.
// ---------------------------------------------------------------------------
#define APITCH 144
#define ASTAGE (128 * APITCH)          // 18432
#define GSTAGE (2 * ASTAGE)            // 36864
#define GEMM_SMEM (3 * GSTAGE)         // 110592

__global__ __launch_bounds__(128, 2)
void gemm_kernel() {
    extern __shared__ char smem[];
    const uint32_t sb = smem_u32(smem);
    const int tid  = threadIdx.x;
    const int lane = tid & 31;
    const int wid  = tid >> 5;
    const int wm   = wid & 1;
    const int wn   = wid >> 1;
    const int mb   = blockIdx.y * 128;
    const int nb   = blockIdx.x * 128;

    const char* Ag = (const char*)d_Acat + (size_t)mb * KB;
    const char* Bg = (const char*)d_Bcat + (size_t)nb * KB;

    float acc[4][8][4];
#pragma unroll
    for (int i = 0; i < 4; i++)
#pragma unroll
        for (int j = 0; j < 8; j++)
#pragma unroll
            for (int q = 0; q < 4; q++) acc[i][j][q] = 0.f;

    auto load_stage = [&](int s, int kt) {
        const uint32_t sA = sb + s * GSTAGE;
        const uint32_t sB = sA + ASTAGE;
        const char* Asrc = Ag + kt * 128;
        const char* Bsrc = Bg + kt * 128;
#pragma unroll
        for (int i = 0; i < 8; i++) {
            int idx = tid + i * 128;
            int row = idx >> 3, seg = idx & 7;
            CP16(sA + row * APITCH + seg * 16, Asrc + (size_t)row * KB + seg * 16);
        }
#pragma unroll
        for (int i = 0; i < 8; i++) {
            int idx = tid + i * 128;
            int row = idx >> 3, seg = idx & 7;
            CP16(sB + row * APITCH + seg * 16, Bsrc + (size_t)row * KB + seg * 16);
        }
    };

    load_stage(0, 0);
    asm volatile("cp.async.commit_group;" ::: "memory");
    load_stage(1, 1);
    asm volatile("cp.async.commit_group;" ::: "memory");

    const uint32_t aoff = (uint32_t)((wm * 64 + (lane & 15)) * APITCH + (lane >> 4) * 16);
    const uint32_t boff = (uint32_t)((wn * 64 + (lane & 7) + ((lane >> 4) & 1) * 8) * APITCH
                                     + ((lane >> 3) & 1) * 16);

    uint32_t af[2][4][4];
    uint32_t bf[2][8][2];

    auto ldsm_ks = [&](uint32_t sA, uint32_t sB, int ks, int buf) {
        const uint32_t kbyte = (uint32_t)ks * 32;
#pragma unroll
        for (int mi = 0; mi < 4; mi++)
            LDSM4(af[buf][mi][0], af[buf][mi][1], af[buf][mi][2], af[buf][mi][3],
                  sA + aoff + mi * (16 * APITCH) + kbyte);
#pragma unroll
        for (int nt = 0; nt < 4; nt++) {
            uint32_t r0, r1, r2, r3;
            LDSM4(r0, r1, r2, r3, sB + boff + nt * (16 * APITCH) + kbyte);
            bf[buf][2 * nt][0] = r0;     bf[buf][2 * nt][1] = r1;
            bf[buf][2 * nt + 1][0] = r2; bf[buf][2 * nt + 1][1] = r3;
        }
    };

    for (int kt = 0; kt < NK2; kt++) {
        const int s = kt % 3;
        asm volatile("cp.async.wait_group 1;" ::: "memory");
        __syncthreads();
        if (kt + 2 < NK2) load_stage((kt + 2) % 3, kt + 2);
        asm volatile("cp.async.commit_group;" ::: "memory");

        const uint32_t sA = sb + s * GSTAGE;
        const uint32_t sB = sA + ASTAGE;
        ldsm_ks(sA, sB, 0, 0);
#pragma unroll
        for (int ks = 0; ks < 4; ks++) {
            const int cur = ks & 1;
            if (ks < 3) ldsm_ks(sA, sB, ks + 1, cur ^ 1);
#pragma unroll
            for (int mi = 0; mi < 4; mi++)
#pragma unroll
                for (int nj = 0; nj < 8; nj++)
                    MMA16816(acc[mi][nj], af[cur][mi], bf[cur][nj]);
        }
    }
    asm volatile("cp.async.wait_group 0;" ::: "memory");

#pragma unroll
    for (int mi = 0; mi < 4; mi++) {
#pragma unroll
        for (int nj = 0; nj < 8; nj++) {
            int row = mb + wm * 64 + mi * 16 + (lane >> 2);
            int col = nb + wn * 64 + nj * 8 + (lane & 3) * 2;
            float* p0 = d_S + (size_t)row * N_TOT + col;
            float* p1 = d_S + (size_t)(row + 8) * N_TOT + col;
            *(float2*)p0 = make_float2(acc[mi][nj][0], acc[mi][nj][1]);
            *(float2*)p1 = make_float2(acc[mi][nj][2], acc[mi][nj][3]);
        }
    }
}

// ---------------------------------------------------------------------------
// merged Gram kernel
// ---------------------------------------------------------------------------
__global__ __launch_bounds__(256)
void gram2_kernel(const float* __restrict__ imgs, const float* __restrict__ caps) {
    const int item = blockIdx.x;
    const bool isCap = item >= N_IMG;
    const float* X = isCap ? caps + (size_t)(item - N_IMG) * N_WORD * DIM
                           : imgs + (size_t)item * N_REG * DIM;
    const int R = isCap ? N_WORD : N_REG;

    __shared__ float xs[36][68];
    const int tid = threadIdx.x;
    const int tr = (tid % 12) * 3;
    const int tc = (tid / 12) * 2;
    const bool act = tid < 216;

    float acc00 = 0.f, acc01 = 0.f, acc10 = 0.f, acc11 = 0.f, acc20 = 0.f, acc21 = 0.f;

    for (int k0 = 0; k0 < DIM; k0 += 64) {
        __syncthreads();
        for (int idx = tid; idx < 36 * 64; idx += 256) {
            int r = idx >> 6, kk = idx & 63;
            xs[r][kk] = (r < R) ? X[(size_t)r * DIM + k0 + kk] : 0.f;
        }
        __syncthreads();
        if (act) {
#pragma unroll 8
            for (int kk = 0; kk < 64; kk++) {
                float a0 = xs[tr][kk], a1 = xs[tr + 1][kk], a2 = xs[tr + 2][kk];
                float b0 = xs[tc][kk], b1 = xs[tc + 1][kk];
                acc00 += a0 * b0; acc01 += a0 * b1;
                acc10 += a1 * b0; acc11 += a1 * b1;
                acc20 += a2 * b0; acc21 += a2 * b1;
            }
        }
    }
    if (act) {
        float* G = isCap ? d_Gc + (size_t)(item - N_IMG) * (N_WORD * N_WORD)
                         : d_Gi + (size_t)item * (N_REG * N_REG);
        float v[3][2] = {{acc00, acc01}, {acc10, acc11}, {acc20, acc21}};
#pragma unroll
        for (int i = 0; i < 3; i++)
#pragma unroll
            for (int j = 0; j < 2; j++) {
                int r = tr + i, c2 = tc + j;
                if (r < R && c2 < R) G[r * R + c2] = v[i][j];
            }
    }
}

// ---------------------------------------------------------------------------
// attention v5: one CTA per (image, caption), 96 threads (3 warps).
// One thread per query; only a[] register-resident (raw S re-read from smem),
// occupancy 4 -> 170-reg budget, no local-memory spills.
// ---------------------------------------------------------------------------
__global__ __launch_bounds__(96, 4)
void attn_kernel(float* __restrict__ out) {
    const int i = blockIdx.x, c = blockIdx.y, tid = threadIdx.x;

    __shared__ float Ss[36][33];
    __shared__ float Gi[36][37];
    __shared__ float Gc[32][33];
    __shared__ float irn_t[36], irn_i[32];
    __shared__ float red[3];

    const float* Sblk = d_S + (size_t)(i * N_REG) * N_TOT + c * N_WORD;
    for (int idx = tid; idx < 36 * 32; idx += 96) {
        int r = idx >> 5, w = idx & 31;
        Ss[r][w] = Sblk[(size_t)r * N_TOT + w];
    }
    const float* gi = d_Gi + (size_t)i * (36 * 36);
    for (int idx = tid; idx < 36 * 36; idx += 96) Gi[idx / 36][idx % 36] = gi[idx];
    const float* gc = d_Gc + (size_t)c * (32 * 32);
    for (int idx = tid; idx < 32 * 32; idx += 96) Gc[idx >> 5][idx & 31] = gc[idx];
    __syncthreads();

    // --- norms of lrelu(S): rows (t2i) and cols (i2t) ---
    if (tid < 36) {
        float s0 = 0.f, s1 = 0.f;
#pragma unroll
        for (int w = 0; w < 32; w += 2) {
            float v0 = lrelu(Ss[tid][w]);     s0 += v0 * v0;
            float v1 = lrelu(Ss[tid][w + 1]); s1 += v1 * v1;
        }
        irn_t[tid] = __fdividef(1.f, sqrtf(s0 + s1) + EPSV);
    } else if (tid < 68) {
        int w = tid - 36;
        float s0 = 0.f, s1 = 0.f;
#pragma unroll
        for (int r = 0; r < 36; r += 2) {
            float v0 = lrelu(Ss[r][w]);     s0 += v0 * v0;
            float v1 = lrelu(Ss[r + 1][w]); s1 += v1 * v1;
        }
        irn_i[w] = __fdividef(1.f, sqrtf(s0 + s1) + EPSV);
    }
    __syncthreads();

    const int wid = tid >> 5, lane = tid & 31;
    float val = 0.f;

    if (wid == 0) {
        // ---- t2i: query = word (lane), context = 36 regions ----
        const int w = lane;
        float a[36];
        float mx = -1e30f;
#pragma unroll
        for (int r = 0; r < 36; r++) {
            float v = lrelu(Ss[r][w]) * irn_t[r];
            a[r] = v; mx = fmaxf(mx, v);
        }
        float esum = 0.f;
#pragma unroll
        for (int r = 0; r < 36; r++) { float e = __expf(LAMBDA * (a[r] - mx)); a[r] = e; esum += e; }
        float th = esum * (1.f / 36.f), tsum = 0.f;
#pragma unroll
        for (int r = 0; r < 36; r++) { float v = (a[r] > th) ? a[r] : 0.f; a[r] = v; tsum += v; }
        float inv = __fdividef(1.f, tsum), num = 0.f;
#pragma unroll
        for (int r = 0; r < 36; r++) { a[r] *= inv; num += a[r] * Ss[r][w]; }
        // quadratic form: a^T Gi a (Gi broadcast across warp)
        float den = 0.f;
#pragma unroll
        for (int r = 0; r < 36; r++) {
            float y0 = 0.f, y1 = 0.f, y2 = 0.f, y3 = 0.f;
#pragma unroll
            for (int q = 0; q < 9; q++) {
                y0 += Gi[r][4 * q + 0] * a[4 * q + 0];
                y1 += Gi[r][4 * q + 1] * a[4 * q + 1];
                y2 += Gi[r][4 * q + 2] * a[4 * q + 2];
                y3 += Gi[r][4 * q + 3] * a[4 * q + 3];
            }
            den += a[r] * ((y0 + y1) + (y2 + y3));
        }
        val = num * __fdividef(1.f,
              fmaxf(sqrtf(Gc[w][w]), EPSV) * fmaxf(sqrtf(den), EPSV));
    } else {
        // ---- i2t: query = region, context = 32 words ----
        const bool valid = (wid == 1) || (lane < 4);
        const int r = valid ? ((wid == 1) ? lane : 32 + lane) : 35;
        float a[32];
        float mx = -1e30f;
#pragma unroll
        for (int w = 0; w < 32; w++) {
            float v = lrelu(Ss[r][w]) * irn_i[w];
            a[w] = v; mx = fmaxf(mx, v);
        }
        float esum = 0.f;
#pragma unroll
        for (int w = 0; w < 32; w++) { float e = __expf(LAMBDA * (a[w] - mx)); a[w] = e; esum += e; }
        float th = esum * (1.f / 32.f), tsum = 0.f;
#pragma unroll
        for (int w = 0; w < 32; w++) { float v = (a[w] > th) ? a[w] : 0.f; a[w] = v; tsum += v; }
        float inv = __fdividef(1.f, tsum), num = 0.f;
#pragma unroll
        for (int w = 0; w < 32; w++) { a[w] *= inv; num += a[w] * Ss[r][w]; }
        float den = 0.f;
#pragma unroll
        for (int w = 0; w < 32; w++) {
            float y0 = 0.f, y1 = 0.f, y2 = 0.f, y3 = 0.f;
#pragma unroll
            for (int q = 0; q < 8; q++) {
                y0 += Gc[w][4 * q + 0] * a[4 * q + 0];
                y1 += Gc[w][4 * q + 1] * a[4 * q + 1];
                y2 += Gc[w][4 * q + 2] * a[4 * q + 2];
                y3 += Gc[w][4 * q + 3] * a[4 * q + 3];
            }
            den += a[w] * ((y0 + y1) + (y2 + y3));
        }
        float v = num * __fdividef(1.f,
                  fmaxf(sqrtf(Gi[r][r]), EPSV) * fmaxf(sqrtf(den), EPSV));
        val = valid ? v : 0.f;
    }

    // warp-level sum
#pragma unroll
    for (int off = 16; off > 0; off >>= 1)
        val += __shfl_xor_sync(0xFFFFFFFFu, val, off);
    if (lane == 0) red[wid] = val;
    __syncthreads();
    if (tid == 0)
        out[i * N_CAP + c] = red[0] * (1.f / 32.f) + (red[1] + red[2]) * (1.f / 36.f);
}

// ---------------------------------------------------------------------------
extern "C" void kernel_launch(void* const* d_in, const int* in_sizes, int n_in,
                              void* d_out, int out_size) {
    const float* images   = (const float*)d_in[0];   // (128,36,1024)
    const float* captions = (const float*)d_in[1];   // (128,32,1024)
    float* out = (float*)d_out;                       // (128,128)

    prep_kernel<<<(M_TOT * DIM / 2) / 256, 256>>>(images, M_TOT * DIM / 2, 0);
    prep_kernel<<<(N_TOT * DIM / 2) / 256, 256>>>(captions, N_TOT * DIM / 2, 1);
    gram2_kernel<<<256, 256>>>(images, captions);

    cudaFuncSetAttribute(gemm_kernel, cudaFuncAttributeMaxDynamicSharedMemorySize, GEMM_SMEM);
    dim3 ggrid(N_TOT / 128, M_TOT / 128);   // (32, 36)
    gemm_kernel<<<ggrid, 128, GEMM_SMEM>>>();

    dim3 agrid(N_IMG, N_CAP);
    attn_kernel<<<agrid, 96>>>(out);
}

// round 9
// speedup vs baseline: 2.2938x; 1.2123x over previous
#include <cuda_runtime.h>
#include <cuda_bf16.h>
#include <math.h>
#include <stdint.h>

#define N_IMG  128
#define N_REG  36
#define N_CAP  128
#define N_WORD 32
#define DIM    1024
#define LAMBDA 20.0f
#define EPSV   1e-8f
#define SLOPE  0.1f

#define M_TOT 4608              // 128*36
#define N_TOT 4096              // 128*32
#define KCAT  3072              // 3 * 1024 (hi/lo concat)
#define KB    (KCAT * 2)        // 6144 bytes per row
#define NK2   48                // KCAT / 64

// ---------------- scratch (static; no cudaMalloc allowed) ----------------
__device__ __align__(256) float         d_S[(size_t)M_TOT * N_TOT];     // 75.5MB
__device__ __align__(256) __nv_bfloat16 d_Acat[(size_t)M_TOT * KCAT];   // [Ah|Ah|Al]
__device__ __align__(256) __nv_bfloat16 d_Bcat[(size_t)N_TOT * KCAT];   // [Bh|Bl|Bh]
__device__ __align__(256) float d_Gi[N_IMG * N_REG * N_REG];
__device__ __align__(256) float d_Gc[N_CAP * N_WORD * N_WORD];

__device__ __forceinline__ float lrelu(float x) { return x > 0.f ? x : SLOPE * x; }

__device__ __forceinline__ uint32_t smem_u32(const void* p) {
    uint32_t a;
    asm("{ .reg .u64 t; cvta.to.shared.u64 t, %1; cvt.u32.u64 %0, t; }" : "=r"(a) : "l"(p));
    return a;
}

#define LDSM4(r0, r1, r2, r3, addr) \
    asm volatile("ldmatrix.sync.aligned.m8n8.x4.shared.b16 {%0,%1,%2,%3}, [%4];" \
        : "=r"(r0), "=r"(r1), "=r"(r2), "=r"(r3) : "r"(addr))

#define MMA16816(d, a, b) \
    asm volatile("mma.sync.aligned.m16n8k16.row.col.f32.bf16.bf16.f32 " \
        "{%0,%1,%2,%3}, {%4,%5,%6,%7}, {%8,%9}, {%0,%1,%2,%3};" \
        : "+f"((d)[0]), "+f"((d)[1]), "+f"((d)[2]), "+f"((d)[3]) \
        : "r"((a)[0]), "r"((a)[1]), "r"((a)[2]), "r"((a)[3]), "r"((b)[0]), "r"((b)[1]))

#define CP16(dst, src) \
    asm volatile("cp.async.cg.shared.global [%0], [%1], 16;" :: "r"(dst), "l"(src))

// ---------------------------------------------------------------------------
// prep (vectorized): fp32 -> bf16 hi/lo concat, 2 elements per thread.
// ---------------------------------------------------------------------------
__global__ void prep_kernel(const float* __restrict__ X, int totalPairs, int sel) {
    int p = blockIdx.x * blockDim.x + threadIdx.x;
    if (p >= totalPairs) return;
    float2 v = *(const float2*)(X + 2 * (size_t)p);
    __nv_bfloat16 h0 = __float2bfloat16(v.x);
    __nv_bfloat16 h1 = __float2bfloat16(v.y);
    __nv_bfloat16 l0 = __float2bfloat16(v.x - __bfloat162float(h0));
    __nv_bfloat16 l1 = __float2bfloat16(v.y - __bfloat162float(h1));
    uint32_t hh = ((uint32_t)*(uint16_t*)&h1 << 16) | *(uint16_t*)&h0;
    uint32_t ll = ((uint32_t)*(uint16_t*)&l1 << 16) | *(uint16_t*)&l0;
    int row = p >> 9, kp = p & 511;
    uint32_t* out = (uint32_t*)(sel ? d_Bcat : d_Acat);
    size_t base = (size_t)row * (KCAT / 2) + kp;
    out[base] = hh;
    out[base + 512]  = sel ? ll : hh;
    out[base + 1024] = sel ? hh : ll;
}

// ---------------------------------------------------------------------------
// bf16 mma.sync GEMM: S = Acat @ Bcat^T, fp32 accum.
// CTA 128x128, BK=64, 3-stage cp.async, 4 warps (2m x 2n), warp tile 64x64.
// ---------------------------------------------------------------------------
#define APITCH 144
#define ASTAGE (128 * APITCH)          // 18432
#define GSTAGE (2 * ASTAGE)            // 36864
#define GEMM_SMEM (3 * GSTAGE)         // 110592

__global__ __launch_bounds__(128, 2)
void gemm_kernel() {
    extern __shared__ char smem[];
    const uint32_t sb = smem_u32(smem);
    const int tid  = threadIdx.x;
    const int lane = tid & 31;
    const int wid  = tid >> 5;
    const int wm   = wid & 1;
    const int wn   = wid >> 1;
    const int mb   = blockIdx.y * 128;
    const int nb   = blockIdx.x * 128;

    const char* Ag = (const char*)d_Acat + (size_t)mb * KB;
    const char* Bg = (const char*)d_Bcat + (size_t)nb * KB;

    float acc[4][8][4];
#pragma unroll
    for (int i = 0; i < 4; i++)
#pragma unroll
        for (int j = 0; j < 8; j++)
#pragma unroll
            for (int q = 0; q < 4; q++) acc[i][j][q] = 0.f;

    auto load_stage = [&](int s, int kt) {
        const uint32_t sA = sb + s * GSTAGE;
        const uint32_t sB = sA + ASTAGE;
        const char* Asrc = Ag + kt * 128;
        const char* Bsrc = Bg + kt * 128;
#pragma unroll
        for (int i = 0; i < 8; i++) {
            int idx = tid + i * 128;
            int row = idx >> 3, seg = idx & 7;
            CP16(sA + row * APITCH + seg * 16, Asrc + (size_t)row * KB + seg * 16);
        }
#pragma unroll
        for (int i = 0; i < 8; i++) {
            int idx = tid + i * 128;
            int row = idx >> 3, seg = idx & 7;
            CP16(sB + row * APITCH + seg * 16, Bsrc + (size_t)row * KB + seg * 16);
        }
    };

    load_stage(0, 0);
    asm volatile("cp.async.commit_group;" ::: "memory");
    load_stage(1, 1);
    asm volatile("cp.async.commit_group;" ::: "memory");

    const uint32_t aoff = (uint32_t)((wm * 64 + (lane & 15)) * APITCH + (lane >> 4) * 16);
    const uint32_t boff = (uint32_t)((wn * 64 + (lane & 7) + ((lane >> 4) & 1) * 8) * APITCH
                                     + ((lane >> 3) & 1) * 16);

    uint32_t af[2][4][4];
    uint32_t bf[2][8][2];

    auto ldsm_ks = [&](uint32_t sA, uint32_t sB, int ks, int buf) {
        const uint32_t kbyte = (uint32_t)ks * 32;
#pragma unroll
        for (int mi = 0; mi < 4; mi++)
            LDSM4(af[buf][mi][0], af[buf][mi][1], af[buf][mi][2], af[buf][mi][3],
                  sA + aoff + mi * (16 * APITCH) + kbyte);
#pragma unroll
        for (int nt = 0; nt < 4; nt++) {
            uint32_t r0, r1, r2, r3;
            LDSM4(r0, r1, r2, r3, sB + boff + nt * (16 * APITCH) + kbyte);
            bf[buf][2 * nt][0] = r0;     bf[buf][2 * nt][1] = r1;
            bf[buf][2 * nt + 1][0] = r2; bf[buf][2 * nt + 1][1] = r3;
        }
    };

    for (int kt = 0; kt < NK2; kt++) {
        const int s = kt % 3;
        asm volatile("cp.async.wait_group 1;" ::: "memory");
        __syncthreads();
        if (kt + 2 < NK2) load_stage((kt + 2) % 3, kt + 2);
        asm volatile("cp.async.commit_group;" ::: "memory");

        const uint32_t sA = sb + s * GSTAGE;
        const uint32_t sB = sA + ASTAGE;
        ldsm_ks(sA, sB, 0, 0);
#pragma unroll
        for (int ks = 0; ks < 4; ks++) {
            const int cur = ks & 1;
            if (ks < 3) ldsm_ks(sA, sB, ks + 1, cur ^ 1);
#pragma unroll
            for (int mi = 0; mi < 4; mi++)
#pragma unroll
                for (int nj = 0; nj < 8; nj++)
                    MMA16816(acc[mi][nj], af[cur][mi], bf[cur][nj]);
        }
    }
    asm volatile("cp.async.wait_group 0;" ::: "memory");

#pragma unroll
    for (int mi = 0; mi < 4; mi++) {
#pragma unroll
        for (int nj = 0; nj < 8; nj++) {
            int row = mb + wm * 64 + mi * 16 + (lane >> 2);
            int col = nb + wn * 64 + nj * 8 + (lane & 3) * 2;
            float* p0 = d_S + (size_t)row * N_TOT + col;
            float* p1 = d_S + (size_t)(row + 8) * N_TOT + col;
            *(float2*)p0 = make_float2(acc[mi][nj][0], acc[mi][nj][1]);
            *(float2*)p1 = make_float2(acc[mi][nj][2], acc[mi][nj][3]);
        }
    }
}

// ---------------------------------------------------------------------------
// merged Gram kernel
// ---------------------------------------------------------------------------
__global__ __launch_bounds__(256)
void gram2_kernel(const float* __restrict__ imgs, const float* __restrict__ caps) {
    const int item = blockIdx.x;
    const bool isCap = item >= N_IMG;
    const float* X = isCap ? caps + (size_t)(item - N_IMG) * N_WORD * DIM
                           : imgs + (size_t)item * N_REG * DIM;
    const int R = isCap ? N_WORD : N_REG;

    __shared__ float xs[36][68];
    const int tid = threadIdx.x;
    const int tr = (tid % 12) * 3;
    const int tc = (tid / 12) * 2;
    const bool act = tid < 216;

    float acc00 = 0.f, acc01 = 0.f, acc10 = 0.f, acc11 = 0.f, acc20 = 0.f, acc21 = 0.f;

    for (int k0 = 0; k0 < DIM; k0 += 64) {
        __syncthreads();
        for (int idx = tid; idx < 36 * 64; idx += 256) {
            int r = idx >> 6, kk = idx & 63;
            xs[r][kk] = (r < R) ? X[(size_t)r * DIM + k0 + kk] : 0.f;
        }
        __syncthreads();
        if (act) {
#pragma unroll 8
            for (int kk = 0; kk < 64; kk++) {
                float a0 = xs[tr][kk], a1 = xs[tr + 1][kk], a2 = xs[tr + 2][kk];
                float b0 = xs[tc][kk], b1 = xs[tc + 1][kk];
                acc00 += a0 * b0; acc01 += a0 * b1;
                acc10 += a1 * b0; acc11 += a1 * b1;
                acc20 += a2 * b0; acc21 += a2 * b1;
            }
        }
    }
    if (act) {
        float* G = isCap ? d_Gc + (size_t)(item - N_IMG) * (N_WORD * N_WORD)
                         : d_Gi + (size_t)item * (N_REG * N_REG);
        float v[3][2] = {{acc00, acc01}, {acc10, acc11}, {acc20, acc21}};
#pragma unroll
        for (int i = 0; i < 3; i++)
#pragma unroll
            for (int j = 0; j < 2; j++) {
                int r = tr + i, c2 = tc + j;
                if (r < R && c2 < R) G[r * R + c2] = v[i][j];
            }
    }
}

// ---------------------------------------------------------------------------
// attention v6: one CTA per (image, caption), 96 threads (3 warps).
// One thread per query, a[] register-resident. Quadratic forms read the Gram
// rows as LDS.128 broadcast (4x fewer shared-memory instructions).
// ---------------------------------------------------------------------------
__global__ __launch_bounds__(96, 4)
void attn_kernel(float* __restrict__ out) {
    const int i = blockIdx.x, c = blockIdx.y, tid = threadIdx.x;

    __shared__ __align__(16) float Ss[36][36];   // pitch 36 (16B aligned rows)
    __shared__ __align__(16) float Gi[36][40];   // pitch 40 (16B aligned rows)
    __shared__ __align__(16) float Gc[32][32];   // pitch 32
    __shared__ float irn_t[36], irn_i[32];
    __shared__ float red[3];

    // --- vectorized fills ---
    const float4* Sblk4 = (const float4*)(d_S + (size_t)(i * N_REG) * N_TOT + c * N_WORD);
    const size_t srow4 = N_TOT / 4;
    for (int idx = tid; idx < 36 * 8; idx += 96) {
        int r = idx >> 3, q = idx & 7;
        *(float4*)&Ss[r][q * 4] = Sblk4[(size_t)r * srow4 + q];
    }
    const float4* gi4 = (const float4*)(d_Gi + (size_t)i * (36 * 36));
    for (int idx = tid; idx < 324; idx += 96) {       // 1296/4
        int e = idx * 4, r = e / 36, col = e - r * 36;
        *(float4*)&Gi[r][col] = gi4[idx];
    }
    const float4* gc4 = (const float4*)(d_Gc + (size_t)c * (32 * 32));
    for (int idx = tid; idx < 256; idx += 96) {       // 1024/4
        ((float4*)Gc)[ (idx >> 3) * 8 + (idx & 7) ] = gc4[idx];
    }
    __syncthreads();

    // --- norms of lrelu(S): rows (t2i) and cols (i2t) ---
    if (tid < 36) {
        float s0 = 0.f, s1 = 0.f;
#pragma unroll
        for (int w = 0; w < 32; w += 2) {
            float v0 = lrelu(Ss[tid][w]);     s0 += v0 * v0;
            float v1 = lrelu(Ss[tid][w + 1]); s1 += v1 * v1;
        }
        irn_t[tid] = __fdividef(1.f, sqrtf(s0 + s1) + EPSV);
    } else if (tid < 68) {
        int w = tid - 36;
        float s0 = 0.f, s1 = 0.f;
#pragma unroll
        for (int r = 0; r < 36; r += 2) {
            float v0 = lrelu(Ss[r][w]);     s0 += v0 * v0;
            float v1 = lrelu(Ss[r + 1][w]); s1 += v1 * v1;
        }
        irn_i[w] = __fdividef(1.f, sqrtf(s0 + s1) + EPSV);
    }
    __syncthreads();

    const int wid = tid >> 5, lane = tid & 31;
    float val = 0.f;

    if (wid == 0) {
        // ---- t2i: query = word (lane), context = 36 regions ----
        const int w = lane;
        float a[36];
        float mx = -1e30f;
#pragma unroll
        for (int r = 0; r < 36; r++) {
            float v = lrelu(Ss[r][w]) * irn_t[r];
            a[r] = v; mx = fmaxf(mx, v);
        }
        float esum = 0.f;
#pragma unroll
        for (int r = 0; r < 36; r++) { float e = __expf(LAMBDA * (a[r] - mx)); a[r] = e; esum += e; }
        float th = esum * (1.f / 36.f), tsum = 0.f;
#pragma unroll
        for (int r = 0; r < 36; r++) { float v = (a[r] > th) ? a[r] : 0.f; a[r] = v; tsum += v; }
        float inv = __fdividef(1.f, tsum), num = 0.f;
#pragma unroll
        for (int r = 0; r < 36; r++) { a[r] *= inv; num += a[r] * Ss[r][w]; }
        // quadratic form: a^T Gi a via LDS.128 broadcast rows
        float den = 0.f;
#pragma unroll
        for (int r = 0; r < 36; r++) {
            const float4* Gr = (const float4*)Gi[r];
            float y0 = 0.f, y1 = 0.f, y2 = 0.f, y3 = 0.f;
#pragma unroll
            for (int q = 0; q < 9; q++) {
                float4 g = Gr[q];
                y0 += g.x * a[4 * q + 0];
                y1 += g.y * a[4 * q + 1];
                y2 += g.z * a[4 * q + 2];
                y3 += g.w * a[4 * q + 3];
            }
            den += a[r] * ((y0 + y1) + (y2 + y3));
        }
        val = num * __fdividef(1.f,
              fmaxf(sqrtf(Gc[w][w]), EPSV) * fmaxf(sqrtf(den), EPSV));
    } else {
        // ---- i2t: query = region, context = 32 words ----
        const bool valid = (wid == 1) || (lane < 4);
        const int r = valid ? ((wid == 1) ? lane : 32 + lane) : 35;
        float a[32];
        float mx = -1e30f;
#pragma unroll
        for (int w = 0; w < 32; w++) {
            float v = lrelu(Ss[r][w]) * irn_i[w];
            a[w] = v; mx = fmaxf(mx, v);
        }
        float esum = 0.f;
#pragma unroll
        for (int w = 0; w < 32; w++) { float e = __expf(LAMBDA * (a[w] - mx)); a[w] = e; esum += e; }
        float th = esum * (1.f / 32.f), tsum = 0.f;
#pragma unroll
        for (int w = 0; w < 32; w++) { float v = (a[w] > th) ? a[w] : 0.f; a[w] = v; tsum += v; }
        float inv = __fdividef(1.f, tsum), num = 0.f;
#pragma unroll
        for (int w = 0; w < 32; w++) { a[w] *= inv; num += a[w] * Ss[r][w]; }
        float den = 0.f;
#pragma unroll
        for (int w = 0; w < 32; w++) {
            const float4* Gr = (const float4*)Gc[w];
            float y0 = 0.f, y1 = 0.f, y2 = 0.f, y3 = 0.f;
#pragma unroll
            for (int q = 0; q < 8; q++) {
                float4 g = Gr[q];
                y0 += g.x * a[4 * q + 0];
                y1 += g.y * a[4 * q + 1];
                y2 += g.z * a[4 * q + 2];
                y3 += g.w * a[4 * q + 3];
            }
            den += a[w] * ((y0 + y1) + (y2 + y3));
        }
        float v = num * __fdividef(1.f,
                  fmaxf(sqrtf(Gi[r][r]), EPSV) * fmaxf(sqrtf(den), EPSV));
        val = valid ? v : 0.f;
    }

    // warp-level sum
#pragma unroll
    for (int off = 16; off > 0; off >>= 1)
        val += __shfl_xor_sync(0xFFFFFFFFu, val, off);
    if (lane == 0) red[wid] = val;
    __syncthreads();
    if (tid == 0)
        out[i * N_CAP + c] = red[0] * (1.f / 32.f) + (red[1] + red[2]) * (1.f / 36.f);
}

// ---------------------------------------------------------------------------
extern "C" void kernel_launch(void* const* d_in, const int* in_sizes, int n_in,
                              void* d_out, int out_size) {
    const float* images   = (const float*)d_in[0];   // (128,36,1024)
    const float* captions = (const float*)d_in[1];   // (128,32,1024)
    float* out = (float*)d_out;                       // (128,128)

    prep_kernel<<<(M_TOT * DIM / 2) / 256, 256>>>(images, M_TOT * DIM / 2, 0);
    prep_kernel<<<(N_TOT * DIM / 2) / 256, 256>>>(captions, N_TOT * DIM / 2, 1);
    gram2_kernel<<<256, 256>>>(images, captions);

    cudaFuncSetAttribute(gemm_kernel, cudaFuncAttributeMaxDynamicSharedMemorySize, GEMM_SMEM);
    dim3 ggrid(N_TOT / 128, M_TOT / 128);   // (32, 36)
    gemm_kernel<<<ggrid, 128, GEMM_SMEM>>>();

    dim3 agrid(N_IMG, N_CAP);
    attn_kernel<<<agrid, 96>>>(out);
}

// round 10
// speedup vs baseline: 2.3578x; 1.0279x over previous
#include <cuda_runtime.h>
#include <cuda_bf16.h>
#include <math.h>
#include <stdint.h>

#define N_IMG  128
#define N_REG  36
#define N_CAP  128
#define N_WORD 32
#define DIM    1024
#define LAMBDA 20.0f
#define EPSV   1e-8f
#define SLOPE  0.1f

#define M_TOT 4608              // 128*36
#define N_TOT 4096              // 128*32
#define KCAT  3072              // 3 * 1024 (hi/lo concat)
#define KB    (KCAT * 2)        // 6144 bytes per row
#define NK2   48                // KCAT / 64

// ---------------- scratch (static; no cudaMalloc allowed) ----------------
__device__ __align__(256) float         d_S[(size_t)M_TOT * N_TOT];     // 75.5MB
__device__ __align__(256) __nv_bfloat16 d_Acat[(size_t)M_TOT * KCAT];   // [Ah|Ah|Al]
__device__ __align__(256) __nv_bfloat16 d_Bcat[(size_t)N_TOT * KCAT];   // [Bh|Bl|Bh]
__device__ __align__(256) float d_Gi[N_IMG * N_REG * N_REG];
__device__ __align__(256) float d_Gc[N_CAP * N_WORD * N_WORD];

__device__ __forceinline__ float lrelu(float x) { return x > 0.f ? x : SLOPE * x; }

__device__ __forceinline__ uint32_t smem_u32(const void* p) {
    uint32_t a;
    asm("{ .reg .u64 t; cvta.to.shared.u64 t, %1; cvt.u32.u64 %0, t; }" : "=r"(a) : "l"(p));
    return a;
}

#define LDSM4(r0, r1, r2, r3, addr) \
    asm volatile("ldmatrix.sync.aligned.m8n8.x4.shared.b16 {%0,%1,%2,%3}, [%4];" \
        : "=r"(r0), "=r"(r1), "=r"(r2), "=r"(r3) : "r"(addr))

#define MMA16816(d, a, b) \
    asm volatile("mma.sync.aligned.m16n8k16.row.col.f32.bf16.bf16.f32 " \
        "{%0,%1,%2,%3}, {%4,%5,%6,%7}, {%8,%9}, {%0,%1,%2,%3};" \
        : "+f"((d)[0]), "+f"((d)[1]), "+f"((d)[2]), "+f"((d)[3]) \
        : "r"((a)[0]), "r"((a)[1]), "r"((a)[2]), "r"((a)[3]), "r"((b)[0]), "r"((b)[1]))

#define CP16(dst, src) \
    asm volatile("cp.async.cg.shared.global [%0], [%1], 16;" :: "r"(dst), "l"(src))

// ---------------------------------------------------------------------------
// prep (vectorized): fp32 -> bf16 hi/lo concat, 2 elements per thread.
// ---------------------------------------------------------------------------
__global__ void prep_kernel(const float* __restrict__ X, int totalPairs, int sel) {
    int p = blockIdx.x * blockDim.x + threadIdx.x;
    if (p >= totalPairs) return;
    float2 v = *(const float2*)(X + 2 * (size_t)p);
    __nv_bfloat16 h0 = __float2bfloat16(v.x);
    __nv_bfloat16 h1 = __float2bfloat16(v.y);
    __nv_bfloat16 l0 = __float2bfloat16(v.x - __bfloat162float(h0));
    __nv_bfloat16 l1 = __float2bfloat16(v.y - __bfloat162float(h1));
    uint32_t hh = ((uint32_t)*(uint16_t*)&h1 << 16) | *(uint16_t*)&h0;
    uint32_t ll = ((uint32_t)*(uint16_t*)&l1 << 16) | *(uint16_t*)&l0;
    int row = p >> 9, kp = p & 511;
    uint32_t* out = (uint32_t*)(sel ? d_Bcat : d_Acat);
    size_t base = (size_t)row * (KCAT / 2) + kp;
    out[base] = hh;
    out[base + 512]  = sel ? ll : hh;
    out[base + 1024] = sel ? hh : ll;
}

// ---------------------------------------------------------------------------
// bf16 mma.sync GEMM: S = Acat @ Bcat^T, fp32 accum.
// CTA 128x128, BK=64, 3-stage cp.async, 4 warps (2m x 2n), warp tile 64x64.
// ---------------------------------------------------------------------------
#define APITCH 144
#define ASTAGE (128 * APITCH)          // 18432
#define GSTAGE (2 * ASTAGE)            // 36864
#define GEMM_SMEM (3 * GSTAGE)         // 110592

__global__ __launch_bounds__(128, 2)
void gemm_kernel() {
    extern __shared__ char smem[];
    const uint32_t sb = smem_u32(smem);
    const int tid  = threadIdx.x;
    const int lane = tid & 31;
    const int wid  = tid >> 5;
    const int wm   = wid & 1;
    const int wn   = wid >> 1;
    const int mb   = blockIdx.y * 128;
    const int nb   = blockIdx.x * 128;

    const char* Ag = (const char*)d_Acat + (size_t)mb * KB;
    const char* Bg = (const char*)d_Bcat + (size_t)nb * KB;

    float acc[4][8][4];
#pragma unroll
    for (int i = 0; i < 4; i++)
#pragma unroll
        for (int j = 0; j < 8; j++)
#pragma unroll
            for (int q = 0; q < 4; q++) acc[i][j][q] = 0.f;

    auto load_stage = [&](int s, int kt) {
        const uint32_t sA = sb + s * GSTAGE;
        const uint32_t sB = sA + ASTAGE;
        const char* Asrc = Ag + kt * 128;
        const char* Bsrc = Bg + kt * 128;
#pragma unroll
        for (int i = 0; i < 8; i++) {
            int idx = tid + i * 128;
            int row = idx >> 3, seg = idx & 7;
            CP16(sA + row * APITCH + seg * 16, Asrc + (size_t)row * KB + seg * 16);
        }
#pragma unroll
        for (int i = 0; i < 8; i++) {
            int idx = tid + i * 128;
            int row = idx >> 3, seg = idx & 7;
            CP16(sB + row * APITCH + seg * 16, Bsrc + (size_t)row * KB + seg * 16);
        }
    };

    load_stage(0, 0);
    asm volatile("cp.async.commit_group;" ::: "memory");
    load_stage(1, 1);
    asm volatile("cp.async.commit_group;" ::: "memory");

    const uint32_t aoff = (uint32_t)((wm * 64 + (lane & 15)) * APITCH + (lane >> 4) * 16);
    const uint32_t boff = (uint32_t)((wn * 64 + (lane & 7) + ((lane >> 4) & 1) * 8) * APITCH
                                     + ((lane >> 3) & 1) * 16);

    uint32_t af[2][4][4];
    uint32_t bf[2][8][2];

    auto ldsm_ks = [&](uint32_t sA, uint32_t sB, int ks, int buf) {
        const uint32_t kbyte = (uint32_t)ks * 32;
#pragma unroll
        for (int mi = 0; mi < 4; mi++)
            LDSM4(af[buf][mi][0], af[buf][mi][1], af[buf][mi][2], af[buf][mi][3],
                  sA + aoff + mi * (16 * APITCH) + kbyte);
#pragma unroll
        for (int nt = 0; nt < 4; nt++) {
            uint32_t r0, r1, r2, r3;
            LDSM4(r0, r1, r2, r3, sB + boff + nt * (16 * APITCH) + kbyte);
            bf[buf][2 * nt][0] = r0;     bf[buf][2 * nt][1] = r1;
            bf[buf][2 * nt + 1][0] = r2; bf[buf][2 * nt + 1][1] = r3;
        }
    };

    for (int kt = 0; kt < NK2; kt++) {
        const int s = kt % 3;
        asm volatile("cp.async.wait_group 1;" ::: "memory");
        __syncthreads();
        if (kt + 2 < NK2) load_stage((kt + 2) % 3, kt + 2);
        asm volatile("cp.async.commit_group;" ::: "memory");

        const uint32_t sA = sb + s * GSTAGE;
        const uint32_t sB = sA + ASTAGE;
        ldsm_ks(sA, sB, 0, 0);
#pragma unroll
        for (int ks = 0; ks < 4; ks++) {
            const int cur = ks & 1;
            if (ks < 3) ldsm_ks(sA, sB, ks + 1, cur ^ 1);
#pragma unroll
            for (int mi = 0; mi < 4; mi++)
#pragma unroll
                for (int nj = 0; nj < 8; nj++)
                    MMA16816(acc[mi][nj], af[cur][mi], bf[cur][nj]);
        }
    }
    asm volatile("cp.async.wait_group 0;" ::: "memory");

#pragma unroll
    for (int mi = 0; mi < 4; mi++) {
#pragma unroll
        for (int nj = 0; nj < 8; nj++) {
            int row = mb + wm * 64 + mi * 16 + (lane >> 2);
            int col = nb + wn * 64 + nj * 8 + (lane & 3) * 2;
            float* p0 = d_S + (size_t)row * N_TOT + col;
            float* p1 = d_S + (size_t)(row + 8) * N_TOT + col;
            *(float2*)p0 = make_float2(acc[mi][nj][0], acc[mi][nj][1]);
            *(float2*)p1 = make_float2(acc[mi][nj][2], acc[mi][nj][3]);
        }
    }
}

// ---------------------------------------------------------------------------
// merged Gram kernel
// ---------------------------------------------------------------------------
__global__ __launch_bounds__(256)
void gram2_kernel(const float* __restrict__ imgs, const float* __restrict__ caps) {
    const int item = blockIdx.x;
    const bool isCap = item >= N_IMG;
    const float* X = isCap ? caps + (size_t)(item - N_IMG) * N_WORD * DIM
                           : imgs + (size_t)item * N_REG * DIM;
    const int R = isCap ? N_WORD : N_REG;

    __shared__ float xs[36][68];
    const int tid = threadIdx.x;
    const int tr = (tid % 12) * 3;
    const int tc = (tid / 12) * 2;
    const bool act = tid < 216;

    float acc00 = 0.f, acc01 = 0.f, acc10 = 0.f, acc11 = 0.f, acc20 = 0.f, acc21 = 0.f;

    for (int k0 = 0; k0 < DIM; k0 += 64) {
        __syncthreads();
        for (int idx = tid; idx < 36 * 64; idx += 256) {
            int r = idx >> 6, kk = idx & 63;
            xs[r][kk] = (r < R) ? X[(size_t)r * DIM + k0 + kk] : 0.f;
        }
        __syncthreads();
        if (act) {
#pragma unroll 8
            for (int kk = 0; kk < 64; kk++) {
                float a0 = xs[tr][kk], a1 = xs[tr + 1][kk], a2 = xs[tr + 2][kk];
                float b0 = xs[tc][kk], b1 = xs[tc + 1][kk];
                acc00 += a0 * b0; acc01 += a0 * b1;
                acc10 += a1 * b0; acc11 += a1 * b1;
                acc20 += a2 * b0; acc21 += a2 * b1;
            }
        }
    }
    if (act) {
        float* G = isCap ? d_Gc + (size_t)(item - N_IMG) * (N_WORD * N_WORD)
                         : d_Gi + (size_t)item * (N_REG * N_REG);
        float v[3][2] = {{acc00, acc01}, {acc10, acc11}, {acc20, acc21}};
#pragma unroll
        for (int i = 0; i < 3; i++)
#pragma unroll
            for (int j = 0; j < 2; j++) {
                int r = tr + i, c2 = tc + j;
                if (r < R && c2 < R) G[r * R + c2] = v[i][j];
            }
    }
}

// ---------------------------------------------------------------------------
// attention v7: one CTA per (image, caption), 96 threads (3 warps).
// Occupancy 6 (18 warps/SM) + 2-way split quadratic-form accumulators.
// ---------------------------------------------------------------------------
__global__ __launch_bounds__(96, 6)
void attn_kernel(float* __restrict__ out) {
    const int i = blockIdx.x, c = blockIdx.y, tid = threadIdx.x;

    __shared__ __align__(16) float Ss[36][36];   // pitch 36 (16B aligned rows)
    __shared__ __align__(16) float Gi[36][40];   // pitch 40 (16B aligned rows)
    __shared__ __align__(16) float Gc[32][32];   // pitch 32
    __shared__ float irn_t[36], irn_i[32];
    __shared__ float red[3];

    // --- vectorized fills ---
    const float4* Sblk4 = (const float4*)(d_S + (size_t)(i * N_REG) * N_TOT + c * N_WORD);
    const size_t srow4 = N_TOT / 4;
    for (int idx = tid; idx < 36 * 8; idx += 96) {
        int r = idx >> 3, q = idx & 7;
        *(float4*)&Ss[r][q * 4] = Sblk4[(size_t)r * srow4 + q];
    }
    const float4* gi4 = (const float4*)(d_Gi + (size_t)i * (36 * 36));
    for (int idx = tid; idx < 324; idx += 96) {       // 1296/4
        int e = idx * 4, r = e / 36, col = e - r * 36;
        *(float4*)&Gi[r][col] = gi4[idx];
    }
    const float4* gc4 = (const float4*)(d_Gc + (size_t)c * (32 * 32));
    for (int idx = tid; idx < 256; idx += 96) {       // 1024/4
        ((float4*)Gc)[ (idx >> 3) * 8 + (idx & 7) ] = gc4[idx];
    }
    __syncthreads();

    // --- norms of lrelu(S): rows (t2i) and cols (i2t) ---
    if (tid < 36) {
        float s0 = 0.f, s1 = 0.f;
#pragma unroll
        for (int w = 0; w < 32; w += 2) {
            float v0 = lrelu(Ss[tid][w]);     s0 += v0 * v0;
            float v1 = lrelu(Ss[tid][w + 1]); s1 += v1 * v1;
        }
        irn_t[tid] = __fdividef(1.f, sqrtf(s0 + s1) + EPSV);
    } else if (tid < 68) {
        int w = tid - 36;
        float s0 = 0.f, s1 = 0.f;
#pragma unroll
        for (int r = 0; r < 36; r += 2) {
            float v0 = lrelu(Ss[r][w]);     s0 += v0 * v0;
            float v1 = lrelu(Ss[r + 1][w]); s1 += v1 * v1;
        }
        irn_i[w] = __fdividef(1.f, sqrtf(s0 + s1) + EPSV);
    }
    __syncthreads();

    const int wid = tid >> 5, lane = tid & 31;
    float val = 0.f;

    if (wid == 0) {
        // ---- t2i: query = word (lane), context = 36 regions ----
        const int w = lane;
        float a[36];
        float mx = -1e30f;
#pragma unroll
        for (int r = 0; r < 36; r++) {
            float v = lrelu(Ss[r][w]) * irn_t[r];
            a[r] = v; mx = fmaxf(mx, v);
        }
        float esum = 0.f;
#pragma unroll
        for (int r = 0; r < 36; r++) { float e = __expf(LAMBDA * (a[r] - mx)); a[r] = e; esum += e; }
        float th = esum * (1.f / 36.f), tsum = 0.f;
#pragma unroll
        for (int r = 0; r < 36; r++) { float v = (a[r] > th) ? a[r] : 0.f; a[r] = v; tsum += v; }
        float inv = __fdividef(1.f, tsum), num = 0.f;
#pragma unroll
        for (int r = 0; r < 36; r++) { a[r] *= inv; num += a[r] * Ss[r][w]; }
        // quadratic form: a^T Gi a via LDS.128 broadcast rows, 2-way outer split
        float den0 = 0.f, den1 = 0.f;
#pragma unroll
        for (int r = 0; r < 36; r += 2) {
            const float4* Gr0 = (const float4*)Gi[r];
            const float4* Gr1 = (const float4*)Gi[r + 1];
            float x0 = 0.f, x1 = 0.f, x2 = 0.f, x3 = 0.f;
            float z0 = 0.f, z1 = 0.f, z2 = 0.f, z3 = 0.f;
#pragma unroll
            for (int q = 0; q < 9; q++) {
                float4 g0 = Gr0[q], g1 = Gr1[q];
                x0 += g0.x * a[4 * q + 0]; z0 += g1.x * a[4 * q + 0];
                x1 += g0.y * a[4 * q + 1]; z1 += g1.y * a[4 * q + 1];
                x2 += g0.z * a[4 * q + 2]; z2 += g1.z * a[4 * q + 2];
                x3 += g0.w * a[4 * q + 3]; z3 += g1.w * a[4 * q + 3];
            }
            den0 += a[r] * ((x0 + x1) + (x2 + x3));
            den1 += a[r + 1] * ((z0 + z1) + (z2 + z3));
        }
        float den = den0 + den1;
        val = num * __fdividef(1.f,
              fmaxf(sqrtf(Gc[w][w]), EPSV) * fmaxf(sqrtf(den), EPSV));
    } else {
        // ---- i2t: query = region, context = 32 words ----
        const bool valid = (wid == 1) || (lane < 4);
        const int r = valid ? ((wid == 1) ? lane : 32 + lane) : 35;
        float a[32];
        float mx = -1e30f;
#pragma unroll
        for (int w = 0; w < 32; w++) {
            float v = lrelu(Ss[r][w]) * irn_i[w];
            a[w] = v; mx = fmaxf(mx, v);
        }
        float esum = 0.f;
#pragma unroll
        for (int w = 0; w < 32; w++) { float e = __expf(LAMBDA * (a[w] - mx)); a[w] = e; esum += e; }
        float th = esum * (1.f / 32.f), tsum = 0.f;
#pragma unroll
        for (int w = 0; w < 32; w++) { float v = (a[w] > th) ? a[w] : 0.f; a[w] = v; tsum += v; }
        float inv = __fdividef(1.f, tsum), num = 0.f;
#pragma unroll
        for (int w = 0; w < 32; w++) { a[w] *= inv; num += a[w] * Ss[r][w]; }
        float den0 = 0.f, den1 = 0.f;
#pragma unroll
        for (int w = 0; w < 32; w += 2) {
            const float4* Gr0 = (const float4*)Gc[w];
            const float4* Gr1 = (const float4*)Gc[w + 1];
            float x0 = 0.f, x1 = 0.f, x2 = 0.f, x3 = 0.f;
            float z0 = 0.f, z1 = 0.f, z2 = 0.f, z3 = 0.f;
#pragma unroll
            for (int q = 0; q < 8; q++) {
                float4 g0 = Gr0[q], g1 = Gr1[q];
                x0 += g0.x * a[4 * q + 0]; z0 += g1.x * a[4 * q + 0];
                x1 += g0.y * a[4 * q + 1]; z1 += g1.y * a[4 * q + 1];
                x2 += g0.z * a[4 * q + 2]; z2 += g1.z * a[4 * q + 2];
                x3 += g0.w * a[4 * q + 3]; z3 += g1.w * a[4 * q + 3];
            }
            den0 += a[w] * ((x0 + x1) + (x2 + x3));
            den1 += a[w + 1] * ((z0 + z1) + (z2 + z3));
        }
        float den = den0 + den1;
        float v = num * __fdividef(1.f,
                  fmaxf(sqrtf(Gi[r][r]), EPSV) * fmaxf(sqrtf(den), EPSV));
        val = valid ? v : 0.f;
    }

    // warp-level sum
#pragma unroll
    for (int off = 16; off > 0; off >>= 1)
        val += __shfl_xor_sync(0xFFFFFFFFu, val, off);
    if (lane == 0) red[wid] = val;
    __syncthreads();
    if (tid == 0)
        out[i * N_CAP + c] = red[0] * (1.f / 32.f) + (red[1] + red[2]) * (1.f / 36.f);
}

// ---------------------------------------------------------------------------
extern "C" void kernel_launch(void* const* d_in, const int* in_sizes, int n_in,
                              void* d_out, int out_size) {
    const float* images   = (const float*)d_in[0];   // (128,36,1024)
    const float* captions = (const float*)d_in[1];   // (128,32,1024)
    float* out = (float*)d_out;                       // (128,128)

    prep_kernel<<<(M_TOT * DIM / 2) / 256, 256>>>(images, M_TOT * DIM / 2, 0);
    prep_kernel<<<(N_TOT * DIM / 2) / 256, 256>>>(captions, N_TOT * DIM / 2, 1);
    gram2_kernel<<<256, 256>>>(images, captions);

    cudaFuncSetAttribute(gemm_kernel, cudaFuncAttributeMaxDynamicSharedMemorySize, GEMM_SMEM);
    dim3 ggrid(N_TOT / 128, M_TOT / 128);   // (32, 36)
    gemm_kernel<<<ggrid, 128, GEMM_SMEM>>>();

    dim3 agrid(N_IMG, N_CAP);
    attn_kernel<<<agrid, 96>>>(out);
}